// round 1
// baseline (speedup 1.0000x reference)
#include <cuda_runtime.h>
#include <cuda_bf16.h>

#define NMAX 100000
#define EMAX 1600000
#define HD   128

// ---------------- scratch (device globals; no allocation allowed) ----------------
__device__ float g_buf0[NMAX * HD];   // ping
__device__ float g_buf1[NMAX * HD];   // pong
__device__ float g_outn[NMAX];
__device__ float g_inn[NMAX];
__device__ float g_hg[HD];
__device__ int   g_degout[NMAX];
__device__ int   g_degin[NMAX];
__device__ int   g_cursor[NMAX];
__device__ int   g_rowptr[NMAX + 1];
__device__ int   g_col[EMAX];
__device__ int   g_bsum[512];
__device__ int   g_boff[512];

// ---------------- init ----------------
__global__ void k_zero(int n) {
    int i = blockIdx.x * blockDim.x + threadIdx.x;
    if (i < n) {
        g_degout[i] = 0;
        g_degin[i]  = 0;
        g_cursor[i] = 0;
    }
    if (i < HD) g_hg[i] = 0.f;
}

// ---------------- degrees ----------------
__global__ void k_deg(const int* __restrict__ src, const int* __restrict__ dst, int e) {
    int i = blockIdx.x * blockDim.x + threadIdx.x;
    if (i < e) {
        atomicAdd(&g_degout[src[i]], 1);
        atomicAdd(&g_degin[dst[i]], 1);
    }
}

__global__ void k_norm(int n) {
    int i = blockIdx.x * blockDim.x + threadIdx.x;
    if (i < n) {
        int dо = g_degout[i]; if (dо < 1) dо = 1;
        int di = g_degin[i];  if (di < 1) di = 1;
        g_outn[i] = rsqrtf((float)dо);
        g_inn[i]  = rsqrtf((float)di);
    }
}

// ---------------- exclusive scan of in-degrees -> row_ptr ----------------
__global__ void k_scan1(int n) {
    __shared__ int sh[512];
    int t = threadIdx.x;
    int i = blockIdx.x * 512 + t;
    int v = (i < n) ? g_degin[i] : 0;
    sh[t] = v;
    __syncthreads();
    #pragma unroll
    for (int off = 1; off < 512; off <<= 1) {
        int x = (t >= off) ? sh[t - off] : 0;
        __syncthreads();
        sh[t] += x;
        __syncthreads();
    }
    if (i < n) g_rowptr[i] = sh[t] - v;   // exclusive, local
    if (t == 511) g_bsum[blockIdx.x] = sh[511];
}

__global__ void k_scan2(int nb, int n) {
    if (threadIdx.x == 0) {
        int run = 0;
        for (int b = 0; b < nb; b++) {
            int v = g_bsum[b];
            g_boff[b] = run;
            run += v;
        }
        g_rowptr[n] = run;
    }
}

__global__ void k_scan3(int n) {
    int i = blockIdx.x * 512 + threadIdx.x;
    if (i < n) g_rowptr[i] += g_boff[blockIdx.x];
}

// ---------------- CSR scatter ----------------
__global__ void k_scatter(const int* __restrict__ src, const int* __restrict__ dst, int e) {
    int i = blockIdx.x * blockDim.x + threadIdx.x;
    if (i < e) {
        int d = dst[i];
        int p = g_rowptr[d] + atomicAdd(&g_cursor[d], 1);
        g_col[p] = src[i];
    }
}

// ---------------- GEMM: Y = (X .* s_row) @ W    (X:[n,128], W:[128,128]) ----------------
__global__ void __launch_bounds__(256) k_gemm(const float* __restrict__ X,
                                              const float* __restrict__ s,
                                              const float* __restrict__ W,
                                              float* __restrict__ Y, int n) {
    __shared__ float  Xs[64][17];
    __shared__ float4 Ws[16][32];
    int t  = threadIdx.x;
    int bm = blockIdx.x * 64;
    int rg = t >> 5;   // 8 rows: rg*8..rg*8+7
    int cg = t & 31;   // 4 cols: cg*4..cg*4+3

    float acc[8][4];
    #pragma unroll
    for (int i = 0; i < 8; i++)
        #pragma unroll
        for (int j = 0; j < 4; j++) acc[i][j] = 0.f;

    int lr = t >> 2, kq = t & 3;       // X-tile loader role
    int gr = bm + lr;
    float sv = (gr < n) ? s[gr] : 0.f;
    const float4* X4 = (const float4*)X;
    const float4* W4 = (const float4*)W;

    for (int k0 = 0; k0 < 128; k0 += 16) {
        float4 xv = make_float4(0.f, 0.f, 0.f, 0.f);
        if (gr < n) xv = X4[gr * 32 + (k0 >> 2) + kq];
        Xs[lr][kq * 4 + 0] = xv.x * sv;
        Xs[lr][kq * 4 + 1] = xv.y * sv;
        Xs[lr][kq * 4 + 2] = xv.z * sv;
        Xs[lr][kq * 4 + 3] = xv.w * sv;
        #pragma unroll
        for (int i = 0; i < 2; i++) {
            int idx = t + i * 256;
            int kk = idx >> 5, cq = idx & 31;
            Ws[kk][cq] = W4[(k0 + kk) * 32 + cq];
        }
        __syncthreads();
        #pragma unroll
        for (int kk = 0; kk < 16; kk++) {
            float4 b = Ws[kk][cg];
            #pragma unroll
            for (int i = 0; i < 8; i++) {
                float a = Xs[rg * 8 + i][kk];
                acc[i][0] = fmaf(a, b.x, acc[i][0]);
                acc[i][1] = fmaf(a, b.y, acc[i][1]);
                acc[i][2] = fmaf(a, b.z, acc[i][2]);
                acc[i][3] = fmaf(a, b.w, acc[i][3]);
            }
        }
        __syncthreads();
    }
    #pragma unroll
    for (int i = 0; i < 8; i++) {
        int r = bm + rg * 8 + i;
        if (r < n)
            ((float4*)Y)[r * 32 + cg] = make_float4(acc[i][0], acc[i][1], acc[i][2], acc[i][3]);
    }
}

// ---------------- aggregation: H[n] = relu(in_norm[n]*sum_{e in row} T[col[e]] + b) ----------------
__global__ void __launch_bounds__(256) k_agg(const float* __restrict__ T,
                                             const float* __restrict__ inn,
                                             const float* __restrict__ bias,
                                             float* __restrict__ Ho, int n) {
    int gw   = (blockIdx.x * 256 + threadIdx.x) >> 5;
    int lane = threadIdx.x & 31;
    if (gw >= n) return;
    int s  = g_rowptr[gw];
    int e2 = g_rowptr[gw + 1];
    const float4* T4 = (const float4*)T;
    float4 a0 = make_float4(0.f, 0.f, 0.f, 0.f);
    float4 a1 = make_float4(0.f, 0.f, 0.f, 0.f);
    int i = s;
    for (; i + 2 <= e2; i += 2) {
        int c0 = g_col[i], c1 = g_col[i + 1];
        float4 v0 = T4[c0 * 32 + lane];
        float4 v1 = T4[c1 * 32 + lane];
        a0.x += v0.x; a0.y += v0.y; a0.z += v0.z; a0.w += v0.w;
        a1.x += v1.x; a1.y += v1.y; a1.z += v1.z; a1.w += v1.w;
    }
    if (i < e2) {
        int c = g_col[i];
        float4 v = T4[c * 32 + lane];
        a0.x += v.x; a0.y += v.y; a0.z += v.z; a0.w += v.w;
    }
    float sc = inn[gw];
    float4 b = ((const float4*)bias)[lane];
    float4 r;
    r.x = fmaxf(fmaf(a0.x + a1.x, sc, b.x), 0.f);
    r.y = fmaxf(fmaf(a0.y + a1.y, sc, b.y), 0.f);
    r.z = fmaxf(fmaf(a0.z + a1.z, sc, b.z), 0.f);
    r.w = fmaxf(fmaf(a0.w + a1.w, sc, b.w), 0.f);
    ((float4*)Ho)[gw * 32 + lane] = r;
}

// ---------------- column sums for mean over nodes ----------------
__global__ void k_colsum(const float* __restrict__ Hf, int n) {
    int t  = threadIdx.x;           // 128
    int r0 = blockIdx.x * 1024;
    int re = r0 + 1024; if (re > n) re = n;
    float sum = 0.f;
    for (int r = r0; r < re; r++) sum += Hf[r * HD + t];
    atomicAdd(&g_hg[t], sum);
}

// ---------------- seg_output ----------------
__global__ void k_seg(const float* __restrict__ Wp, const float* __restrict__ bp,
                      float* __restrict__ out, int n) {
    int c = threadIdx.x;
    if (c < 40) {
        float inv = 1.f / (float)n;
        float sum = bp[c];
        for (int k = 0; k < HD; k++) sum = fmaf(g_hg[k] * inv, Wp[c * HD + k], sum);
        out[c] = sum;
    }
}

// ---------------- CAM: out[c*n + node] = dot(Wp[c,:], H[node,:]) ----------------
__global__ void __launch_bounds__(256) k_cam(const float* __restrict__ Hf,
                                             const float* __restrict__ Wp,
                                             float* __restrict__ out, int n) {
    __shared__ float Ws[40 * HD];      // 20 KB
    __shared__ float Hs[64][33];       // 8.4 KB (k-chunked)
    int t = threadIdx.x;
    for (int i = t; i < 40 * HD; i += 256) Ws[i] = Wp[i];

    int base = blockIdx.x * 64;
    int ng = t & 31;                   // nodes 2*ng, 2*ng+1
    int cg = t >> 5;                   // classes 5*cg..5*cg+4
    int n0 = base + 2 * ng, n1 = n0 + 1;
    float acc0[5], acc1[5];
    #pragma unroll
    for (int j = 0; j < 5; j++) { acc0[j] = 0.f; acc1[j] = 0.f; }

    const float4* H4 = (const float4*)Hf;
    for (int k0 = 0; k0 < 128; k0 += 32) {
        __syncthreads();               // also covers initial Ws load
        #pragma unroll
        for (int i = 0; i < 2; i++) {
            int idx = t + i * 256;     // 0..511 : 64 rows x 8 float4
            int row = idx >> 3, q = idx & 7;
            int gr = base + row;
            float4 v = make_float4(0.f, 0.f, 0.f, 0.f);
            if (gr < n) v = H4[gr * 32 + (k0 >> 2) + q];
            Hs[row][q * 4 + 0] = v.x;
            Hs[row][q * 4 + 1] = v.y;
            Hs[row][q * 4 + 2] = v.z;
            Hs[row][q * 4 + 3] = v.w;
        }
        __syncthreads();
        #pragma unroll
        for (int kk = 0; kk < 32; kk++) {
            float a0 = Hs[2 * ng][kk];
            float a1 = Hs[2 * ng + 1][kk];
            #pragma unroll
            for (int j = 0; j < 5; j++) {
                float b = Ws[(5 * cg + j) * HD + k0 + kk];
                acc0[j] = fmaf(a0, b, acc0[j]);
                acc1[j] = fmaf(a1, b, acc1[j]);
            }
        }
    }
    #pragma unroll
    for (int j = 0; j < 5; j++) {
        int c = 5 * cg + j;
        if (n0 < n) out[c * n + n0] = acc0[j];
        if (n1 < n) out[c * n + n1] = acc1[j];
    }
}

// ---------------- launch ----------------
extern "C" void kernel_launch(void* const* d_in, const int* in_sizes, int n_in,
                              void* d_out, int out_size) {
    const float* features = (const float*)d_in[0];
    const float* W1 = (const float*)d_in[1];
    const float* b1 = (const float*)d_in[2];
    const float* W2 = (const float*)d_in[3];
    const float* b2 = (const float*)d_in[4];
    const float* W3 = (const float*)d_in[5];
    const float* b3 = (const float*)d_in[6];
    const float* Wp = (const float*)d_in[7];
    const float* bp = (const float*)d_in[8];
    const int*  src = (const int*)d_in[9];
    const int*  dst = (const int*)d_in[10];
    float* out = (float*)d_out;

    int n = in_sizes[0] / HD;          // 100000
    int e = in_sizes[9];               // 1600000

    int gn  = (n + 255) / 256;
    int ge  = (e + 255) / 256;
    int nb  = (n + 511) / 512;

    float *buf0, *buf1, *outn, *inn;
    cudaGetSymbolAddress((void**)&buf0, g_buf0);
    cudaGetSymbolAddress((void**)&buf1, g_buf1);
    cudaGetSymbolAddress((void**)&outn, g_outn);
    cudaGetSymbolAddress((void**)&inn,  g_inn);

    k_zero<<<gn, 256>>>(n);
    k_deg<<<ge, 256>>>(src, dst, e);
    k_norm<<<gn, 256>>>(n);
    k_scan1<<<nb, 512>>>(n);
    k_scan2<<<1, 32>>>(nb, n);
    k_scan3<<<nb, 512>>>(n);
    k_scatter<<<ge, 256>>>(src, dst, e);

    int gg = (n + 63) / 64;
    int ga = (n + 7) / 8;

    // layer 1
    k_gemm<<<gg, 256>>>(features, outn, W1, buf0, n);
    k_agg<<<ga, 256>>>(buf0, inn, b1, buf1, n);
    // layer 2
    k_gemm<<<gg, 256>>>(buf1, outn, W2, buf0, n);
    k_agg<<<ga, 256>>>(buf0, inn, b2, buf1, n);
    // layer 3
    k_gemm<<<gg, 256>>>(buf1, outn, W3, buf0, n);
    k_agg<<<ga, 256>>>(buf0, inn, b3, buf1, n);

    // heads
    k_colsum<<<(n + 1023) / 1024, 128>>>(buf1, n);
    k_seg<<<1, 64>>>(Wp, bp, out, n);
    k_cam<<<gg, 256>>>(buf1, Wp, out + 40, n);
}

// round 3
// speedup vs baseline: 1.1151x; 1.1151x over previous
#include <cuda_runtime.h>
#include <cuda_fp16.h>
#include <cuda_bf16.h>
#include <cstdint>

#define NMAX 100000
#define EMAX 1600000
#define HD   128

// ---------------- scratch (device globals; no allocation allowed) ----------------
__device__ float g_buf0[NMAX * HD];   // ping
__device__ float g_buf1[NMAX * HD];   // pong
__device__ float g_outn[NMAX];
__device__ float g_inn[NMAX];
__device__ float g_hg[HD];
__device__ int   g_degout[NMAX];
__device__ int   g_degin[NMAX];
__device__ int   g_cursor[NMAX];
__device__ int   g_rowptr[NMAX + 1];
__device__ int   g_col[EMAX];
__device__ int   g_bsum[512];
__device__ int   g_boff[512];
__device__ __half g_wt1[HD * HD];     // W1^T fp16: [n][k]
__device__ __half g_wt2[HD * HD];
__device__ __half g_wt3[HD * HD];

// ================= warp MMA helpers (baseline PTX, compiles on compute_103) ====
__device__ __forceinline__ uint32_t smem_u32(const void* p) {
    uint32_t a;
    asm("{ .reg .u64 t; cvta.to.shared.u64 t, %1; cvt.u32.u64 %0, t; }" : "=r"(a) : "l"(p));
    return a;
}
__device__ __forceinline__ void ldsm_x4(uint32_t* r, uint32_t addr) {
    asm volatile("ldmatrix.sync.aligned.m8n8.x4.shared.b16 {%0,%1,%2,%3}, [%4];"
                 : "=r"(r[0]), "=r"(r[1]), "=r"(r[2]), "=r"(r[3]) : "r"(addr));
}
__device__ __forceinline__ void mma_f16(float* d, const uint32_t* a, uint32_t b0, uint32_t b1) {
    asm volatile("mma.sync.aligned.m16n8k16.row.col.f32.f16.f16.f32 "
                 "{%0,%1,%2,%3}, {%4,%5,%6,%7}, {%8,%9}, {%0,%1,%2,%3};"
                 : "+f"(d[0]), "+f"(d[1]), "+f"(d[2]), "+f"(d[3])
                 : "r"(a[0]), "r"(a[1]), "r"(a[2]), "r"(a[3]), "r"(b0), "r"(b1));
}

#define SSTR 136   // smem row stride in halves (272B: 16B-aligned, conflict-free ldmatrix)
#define MM_SMEM (2 * 128 * SSTR * 2)

// ---------------- init ----------------
__global__ void k_zero(int n) {
    int i = blockIdx.x * blockDim.x + threadIdx.x;
    if (i < n) {
        g_degout[i] = 0;
        g_degin[i]  = 0;
        g_cursor[i] = 0;
    }
    if (i < HD) g_hg[i] = 0.f;
}

// ---------------- degrees ----------------
__global__ void k_deg(const int* __restrict__ src, const int* __restrict__ dst, int e) {
    int i = blockIdx.x * blockDim.x + threadIdx.x;
    if (i < e) {
        atomicAdd(&g_degout[src[i]], 1);
        atomicAdd(&g_degin[dst[i]], 1);
    }
}

__global__ void k_norm(int n) {
    int i = blockIdx.x * blockDim.x + threadIdx.x;
    if (i < n) {
        int a = g_degout[i]; if (a < 1) a = 1;
        int b = g_degin[i];  if (b < 1) b = 1;
        g_outn[i] = rsqrtf((float)a);
        g_inn[i]  = rsqrtf((float)b);
    }
}

// ---------------- weight transpose + fp16 convert ----------------
__global__ void k_prepw(const float* __restrict__ W1, const float* __restrict__ W2,
                        const float* __restrict__ W3) {
    int t = blockIdx.x * 256 + threadIdx.x;
    if (t < HD * HD) {
        int k = t >> 7, n = t & 127;   // t = k*128 + n
        g_wt1[n * HD + k] = __float2half(W1[t]);
        g_wt2[n * HD + k] = __float2half(W2[t]);
        g_wt3[n * HD + k] = __float2half(W3[t]);
    }
}

// ---------------- exclusive scan of in-degrees -> row_ptr ----------------
__global__ void k_scan1(int n) {
    __shared__ int sh[512];
    int t = threadIdx.x;
    int i = blockIdx.x * 512 + t;
    int v = (i < n) ? g_degin[i] : 0;
    sh[t] = v;
    __syncthreads();
    #pragma unroll
    for (int off = 1; off < 512; off <<= 1) {
        int x = (t >= off) ? sh[t - off] : 0;
        __syncthreads();
        sh[t] += x;
        __syncthreads();
    }
    if (i < n) g_rowptr[i] = sh[t] - v;
    if (t == 511) g_bsum[blockIdx.x] = sh[511];
}

__global__ void k_scan2(int nb, int n) {
    if (threadIdx.x == 0) {
        int run = 0;
        for (int b = 0; b < nb; b++) {
            int v = g_bsum[b];
            g_boff[b] = run;
            run += v;
        }
        g_rowptr[n] = run;
    }
}

__global__ void k_scan3(int n) {
    int i = blockIdx.x * 512 + threadIdx.x;
    if (i < n) g_rowptr[i] += g_boff[blockIdx.x];
}

// ---------------- CSR scatter ----------------
__global__ void k_scatter(const int* __restrict__ src, const int* __restrict__ dst, int e) {
    int i = blockIdx.x * blockDim.x + threadIdx.x;
    if (i < e) {
        int d = dst[i];
        int p = g_rowptr[d] + atomicAdd(&g_cursor[d], 1);
        g_col[p] = src[i];
    }
}

// ------------- HMMA GEMM: Y[128-tile,128] = (X .* s) @ W  (fp16 in, fp32 acc) -------------
__global__ void __launch_bounds__(256) k_mm(const float* __restrict__ X,
                                            const float* __restrict__ s,
                                            const __half* __restrict__ Wt,
                                            float* __restrict__ Y, int n) {
    extern __shared__ __half sh[];
    __half* As = sh;                       // 128 x SSTR
    __half* Bs = sh + 128 * SSTR;          // 128 x SSTR  (Wt rows: [n][k])
    int tid = threadIdx.x;
    int base = blockIdx.x * 128;

    // ---- load X (fp32 -> fp16 * out_norm) ----
    const float4* X4 = (const float4*)X;
    #pragma unroll
    for (int i = 0; i < 8; i++) {
        int slot = i * 256 + tid;          // 2048 slots: row = slot/16, 8-col group j = slot%16
        int row = slot >> 4, j = slot & 15;
        int gr = base + row;
        float4 a = make_float4(0.f, 0.f, 0.f, 0.f);
        float4 b = make_float4(0.f, 0.f, 0.f, 0.f);
        float sv = 0.f;
        if (gr < n) {
            sv = s[gr];
            a = X4[gr * 32 + j * 2];
            b = X4[gr * 32 + j * 2 + 1];
        }
        __align__(16) __half2 h[4];
        h[0] = __floats2half2_rn(a.x * sv, a.y * sv);
        h[1] = __floats2half2_rn(a.z * sv, a.w * sv);
        h[2] = __floats2half2_rn(b.x * sv, b.y * sv);
        h[3] = __floats2half2_rn(b.z * sv, b.w * sv);
        *(uint4*)(As + row * SSTR + j * 8) = *(uint4*)h;
    }
    // ---- load W^T fp16 ----
    const uint4* Wt4 = (const uint4*)Wt;
    #pragma unroll
    for (int i = 0; i < 8; i++) {
        int slot = i * 256 + tid;
        int row = slot >> 4, j = slot & 15;
        uint4 v = Wt4[slot];
        *(uint4*)(Bs + row * SSTR + j * 8) = v;
    }
    __syncthreads();

    int lane = tid & 31;
    int w = tid >> 5;
    int wm = (w & 3) * 32;     // row block
    int wn = (w >> 2) * 64;    // col block

    float acc[2][8][4];
    #pragma unroll
    for (int mi = 0; mi < 2; mi++)
        #pragma unroll
        for (int ni = 0; ni < 8; ni++)
            #pragma unroll
            for (int q = 0; q < 4; q++) acc[mi][ni][q] = 0.f;

    uint32_t a_base = smem_u32(As);
    uint32_t b_base = smem_u32(Bs);

    #pragma unroll
    for (int k0 = 0; k0 < 128; k0 += 16) {
        uint32_t af[2][4];
        #pragma unroll
        for (int mi = 0; mi < 2; mi++) {
            int row = wm + mi * 16 + (lane & 15);
            int col = k0 + (lane >> 4) * 8;
            ldsm_x4(af[mi], a_base + (uint32_t)(row * SSTR + col) * 2);
        }
        uint32_t bf[4][4];
        #pragma unroll
        for (int p = 0; p < 4; p++) {
            int row = wn + p * 16 + ((lane >> 4) & 1) * 8 + (lane & 7);
            int col = k0 + ((lane >> 3) & 1) * 8;
            ldsm_x4(bf[p], b_base + (uint32_t)(row * SSTR + col) * 2);
        }
        #pragma unroll
        for (int mi = 0; mi < 2; mi++)
            #pragma unroll
            for (int p = 0; p < 4; p++) {
                mma_f16(acc[mi][2 * p],     af[mi], bf[p][0], bf[p][1]);
                mma_f16(acc[mi][2 * p + 1], af[mi], bf[p][2], bf[p][3]);
            }
    }

    // ---- store fp32 ----
    float2* Y2 = (float2*)Y;
    #pragma unroll
    for (int mi = 0; mi < 2; mi++) {
        int r0 = base + wm + mi * 16 + (lane >> 2);
        int r1 = r0 + 8;
        #pragma unroll
        for (int ni = 0; ni < 8; ni++) {
            int col = wn + ni * 8 + (lane & 3) * 2;
            if (r0 < n) Y2[(r0 * 128 + col) >> 1] = make_float2(acc[mi][ni][0], acc[mi][ni][1]);
            if (r1 < n) Y2[(r1 * 128 + col) >> 1] = make_float2(acc[mi][ni][2], acc[mi][ni][3]);
        }
    }
}

// ---------------- aggregation: H[n] = relu(in_norm[n]*sum_{e in row} T[col[e]] + b) ----------------
__global__ void __launch_bounds__(256) k_agg(const float* __restrict__ T,
                                             const float* __restrict__ inn,
                                             const float* __restrict__ bias,
                                             float* __restrict__ Ho, int n) {
    int gw   = (blockIdx.x * 256 + threadIdx.x) >> 5;
    int lane = threadIdx.x & 31;
    if (gw >= n) return;
    int s  = g_rowptr[gw];
    int e2 = g_rowptr[gw + 1];
    const float4* T4 = (const float4*)T;
    float4 a0 = make_float4(0.f, 0.f, 0.f, 0.f);
    float4 a1 = make_float4(0.f, 0.f, 0.f, 0.f);
    int i = s;
    for (; i + 2 <= e2; i += 2) {
        int c0 = g_col[i], c1 = g_col[i + 1];
        float4 v0 = T4[c0 * 32 + lane];
        float4 v1 = T4[c1 * 32 + lane];
        a0.x += v0.x; a0.y += v0.y; a0.z += v0.z; a0.w += v0.w;
        a1.x += v1.x; a1.y += v1.y; a1.z += v1.z; a1.w += v1.w;
    }
    if (i < e2) {
        int c = g_col[i];
        float4 v = T4[c * 32 + lane];
        a0.x += v.x; a0.y += v.y; a0.z += v.z; a0.w += v.w;
    }
    float sc = inn[gw];
    float4 b = ((const float4*)bias)[lane];
    float4 r;
    r.x = fmaxf(fmaf(a0.x + a1.x, sc, b.x), 0.f);
    r.y = fmaxf(fmaf(a0.y + a1.y, sc, b.y), 0.f);
    r.z = fmaxf(fmaf(a0.z + a1.z, sc, b.z), 0.f);
    r.w = fmaxf(fmaf(a0.w + a1.w, sc, b.w), 0.f);
    ((float4*)Ho)[gw * 32 + lane] = r;
}

// ---------------- column sums for mean over nodes ----------------
__global__ void k_colsum(const float* __restrict__ Hf, int n) {
    int t  = threadIdx.x;           // 128
    int r0 = blockIdx.x * 1024;
    int re = r0 + 1024; if (re > n) re = n;
    float sum = 0.f;
    for (int r = r0; r < re; r++) sum += Hf[r * HD + t];
    atomicAdd(&g_hg[t], sum);
}

// ---------------- seg_output ----------------
__global__ void k_seg(const float* __restrict__ Wp, const float* __restrict__ bp,
                      float* __restrict__ out, int n) {
    int c = threadIdx.x;
    if (c < 40) {
        float inv = 1.f / (float)n;
        float sum = bp[c];
        for (int k = 0; k < HD; k++) sum = fmaf(g_hg[k] * inv, Wp[c * HD + k], sum);
        out[c] = sum;
    }
}

// ---------------- CAM: out[c*n + node] = dot(Wp[c,:], H[node,:]) ----------------
__global__ void __launch_bounds__(256) k_cam(const float* __restrict__ Hf,
                                             const float* __restrict__ Wp,
                                             float* __restrict__ out, int n) {
    __shared__ float Ws[40 * HD];      // 20 KB
    __shared__ float Hs[64][33];       // 8.4 KB (k-chunked)
    int t = threadIdx.x;
    for (int i = t; i < 40 * HD; i += 256) Ws[i] = Wp[i];

    int base = blockIdx.x * 64;
    int ng = t & 31;
    int cg = t >> 5;
    int n0 = base + 2 * ng, n1 = n0 + 1;
    float acc0[5], acc1[5];
    #pragma unroll
    for (int j = 0; j < 5; j++) { acc0[j] = 0.f; acc1[j] = 0.f; }

    const float4* H4 = (const float4*)Hf;
    for (int k0 = 0; k0 < 128; k0 += 32) {
        __syncthreads();
        #pragma unroll
        for (int i = 0; i < 2; i++) {
            int idx = t + i * 256;
            int row = idx >> 3, q = idx & 7;
            int gr = base + row;
            float4 v = make_float4(0.f, 0.f, 0.f, 0.f);
            if (gr < n) v = H4[gr * 32 + (k0 >> 2) + q];
            Hs[row][q * 4 + 0] = v.x;
            Hs[row][q * 4 + 1] = v.y;
            Hs[row][q * 4 + 2] = v.z;
            Hs[row][q * 4 + 3] = v.w;
        }
        __syncthreads();
        #pragma unroll
        for (int kk = 0; kk < 32; kk++) {
            float a0 = Hs[2 * ng][kk];
            float a1 = Hs[2 * ng + 1][kk];
            #pragma unroll
            for (int j = 0; j < 5; j++) {
                float b = Ws[(5 * cg + j) * HD + k0 + kk];
                acc0[j] = fmaf(a0, b, acc0[j]);
                acc1[j] = fmaf(a1, b, acc1[j]);
            }
        }
    }
    #pragma unroll
    for (int j = 0; j < 5; j++) {
        int c = 5 * cg + j;
        if (n0 < n) out[c * n + n0] = acc0[j];
        if (n1 < n) out[c * n + n1] = acc1[j];
    }
}

// ---------------- launch ----------------
extern "C" void kernel_launch(void* const* d_in, const int* in_sizes, int n_in,
                              void* d_out, int out_size) {
    const float* features = (const float*)d_in[0];
    const float* W1 = (const float*)d_in[1];
    const float* b1 = (const float*)d_in[2];
    const float* W2 = (const float*)d_in[3];
    const float* b2 = (const float*)d_in[4];
    const float* W3 = (const float*)d_in[5];
    const float* b3 = (const float*)d_in[6];
    const float* Wp = (const float*)d_in[7];
    const float* bp = (const float*)d_in[8];
    const int*  src = (const int*)d_in[9];
    const int*  dst = (const int*)d_in[10];
    float* out = (float*)d_out;

    int n = in_sizes[0] / HD;          // 100000
    int e = in_sizes[9];               // 1600000

    int gn  = (n + 255) / 256;
    int ge  = (e + 255) / 256;
    int nb  = (n + 511) / 512;

    float *buf0, *buf1, *outn, *inn;
    __half *wt1, *wt2, *wt3;
    cudaGetSymbolAddress((void**)&buf0, g_buf0);
    cudaGetSymbolAddress((void**)&buf1, g_buf1);
    cudaGetSymbolAddress((void**)&outn, g_outn);
    cudaGetSymbolAddress((void**)&inn,  g_inn);
    cudaGetSymbolAddress((void**)&wt1,  g_wt1);
    cudaGetSymbolAddress((void**)&wt2,  g_wt2);
    cudaGetSymbolAddress((void**)&wt3,  g_wt3);

    cudaFuncSetAttribute(k_mm, cudaFuncAttributeMaxDynamicSharedMemorySize, MM_SMEM);

    k_zero<<<gn, 256>>>(n);
    k_deg<<<ge, 256>>>(src, dst, e);
    k_norm<<<gn, 256>>>(n);
    k_prepw<<<(HD * HD + 255) / 256, 256>>>(W1, W2, W3);
    k_scan1<<<nb, 512>>>(n);
    k_scan2<<<1, 32>>>(nb, n);
    k_scan3<<<nb, 512>>>(n);
    k_scatter<<<ge, 256>>>(src, dst, e);

    int gt = (n + 127) / 128;   // GEMM tiles
    int ga = (n + 7) / 8;
    int gg = (n + 63) / 64;

    // layer 1
    k_mm<<<gt, 256, MM_SMEM>>>(features, outn, wt1, buf0, n);
    k_agg<<<ga, 256>>>(buf0, inn, b1, buf1, n);
    // layer 2
    k_mm<<<gt, 256, MM_SMEM>>>(buf1, outn, wt2, buf0, n);
    k_agg<<<ga, 256>>>(buf0, inn, b2, buf1, n);
    // layer 3
    k_mm<<<gt, 256, MM_SMEM>>>(buf1, outn, wt3, buf0, n);
    k_agg<<<ga, 256>>>(buf0, inn, b3, buf1, n);

    // heads
    k_colsum<<<(n + 1023) / 1024, 128>>>(buf1, n);
    k_seg<<<1, 64>>>(Wp, bp, out, n);
    k_cam<<<gg, 256>>>(buf1, Wp, out + 40, n);
}

// round 4
// speedup vs baseline: 1.7412x; 1.5614x over previous
#include <cuda_runtime.h>
#include <cuda_fp16.h>
#include <cuda_bf16.h>
#include <cstdint>

#define NMAX 100000
#define EMAX 1600000
#define HD   128

// ---------------- scratch (device globals; no allocation allowed) ----------------
__device__ float  g_buf0[NMAX * HD];    // fp32 H (final layer, for heads)
__device__ __half g_h16a[NMAX * HD];    // fp16 hidden (pre-scaled by out_norm)
__device__ __half g_h16b[NMAX * HD];
__device__ __half g_m16[NMAX * HD];     // fp16 messages (GEMM output)
__device__ float g_outn[NMAX];
__device__ float g_inn[NMAX];
__device__ float g_hg[HD];
__device__ int   g_degout[NMAX];
__device__ int   g_degin[NMAX];
__device__ int   g_cursor[NMAX];
__device__ int   g_rowptr[NMAX + 1];
__device__ int   g_col[EMAX];
__device__ int   g_bsum[512];
__device__ int   g_boff[512];
__device__ __half g_wt1[HD * HD];       // W^T fp16: [n][k]
__device__ __half g_wt2[HD * HD];
__device__ __half g_wt3[HD * HD];

// ================= warp MMA helpers (baseline PTX, compiles on compute_103) ====
__device__ __forceinline__ uint32_t smem_u32(const void* p) {
    uint32_t a;
    asm("{ .reg .u64 t; cvta.to.shared.u64 t, %1; cvt.u32.u64 %0, t; }" : "=r"(a) : "l"(p));
    return a;
}
__device__ __forceinline__ void ldsm_x4(uint32_t* r, uint32_t addr) {
    asm volatile("ldmatrix.sync.aligned.m8n8.x4.shared.b16 {%0,%1,%2,%3}, [%4];"
                 : "=r"(r[0]), "=r"(r[1]), "=r"(r[2]), "=r"(r[3]) : "r"(addr));
}
__device__ __forceinline__ void mma_f16(float* d, const uint32_t* a, uint32_t b0, uint32_t b1) {
    asm volatile("mma.sync.aligned.m16n8k16.row.col.f32.f16.f16.f32 "
                 "{%0,%1,%2,%3}, {%4,%5,%6,%7}, {%8,%9}, {%0,%1,%2,%3};"
                 : "+f"(d[0]), "+f"(d[1]), "+f"(d[2]), "+f"(d[3])
                 : "r"(a[0]), "r"(a[1]), "r"(a[2]), "r"(a[3]), "r"(b0), "r"(b1));
}

#define SSTR 136   // smem row stride in halves (272B: 16B-aligned, conflict-free ldmatrix)
#define MM_SMEM (2 * 128 * SSTR * 2)

// ---------------- init ----------------
__global__ void k_zero(int n) {
    int i = blockIdx.x * blockDim.x + threadIdx.x;
    if (i < n) {
        g_degout[i] = 0;
        g_degin[i]  = 0;
        g_cursor[i] = 0;
    }
    if (i < HD) g_hg[i] = 0.f;
}

// ---------------- degrees ----------------
__global__ void k_deg(const int* __restrict__ src, const int* __restrict__ dst, int e) {
    int i = blockIdx.x * blockDim.x + threadIdx.x;
    if (i < e) {
        atomicAdd(&g_degout[src[i]], 1);
        atomicAdd(&g_degin[dst[i]], 1);
    }
}

__global__ void k_norm(int n) {
    int i = blockIdx.x * blockDim.x + threadIdx.x;
    if (i < n) {
        int a = g_degout[i]; if (a < 1) a = 1;
        int b = g_degin[i];  if (b < 1) b = 1;
        g_outn[i] = rsqrtf((float)a);
        g_inn[i]  = rsqrtf((float)b);
    }
}

// ---------------- weight transpose + fp16 convert ----------------
__global__ void k_prepw(const float* __restrict__ W1, const float* __restrict__ W2,
                        const float* __restrict__ W3) {
    int t = blockIdx.x * 256 + threadIdx.x;
    if (t < HD * HD) {
        int k = t >> 7, n = t & 127;   // t = k*128 + n
        g_wt1[n * HD + k] = __float2half(W1[t]);
        g_wt2[n * HD + k] = __float2half(W2[t]);
        g_wt3[n * HD + k] = __float2half(W3[t]);
    }
}

// ---------------- features * out_norm -> fp16 ----------------
__global__ void k_prepx(const float* __restrict__ X, __half* __restrict__ Xh, int n) {
    int i = blockIdx.x * 256 + threadIdx.x;   // one float4 (4 cols) per thread
    if (i < n * 32) {
        float sv = g_outn[i >> 5];
        float4 a = ((const float4*)X)[i];
        __half2 h0 = __floats2half2_rn(a.x * sv, a.y * sv);
        __half2 h1 = __floats2half2_rn(a.z * sv, a.w * sv);
        ((__half2*)Xh)[i * 2]     = h0;
        ((__half2*)Xh)[i * 2 + 1] = h1;
    }
}

// ---------------- exclusive scan of in-degrees -> row_ptr ----------------
__global__ void k_scan1(int n) {
    __shared__ int sh[512];
    int t = threadIdx.x;
    int i = blockIdx.x * 512 + t;
    int v = (i < n) ? g_degin[i] : 0;
    sh[t] = v;
    __syncthreads();
    #pragma unroll
    for (int off = 1; off < 512; off <<= 1) {
        int x = (t >= off) ? sh[t - off] : 0;
        __syncthreads();
        sh[t] += x;
        __syncthreads();
    }
    if (i < n) g_rowptr[i] = sh[t] - v;
    if (t == 511) g_bsum[blockIdx.x] = sh[511];
}

__global__ void k_scan2(int nb, int n) {
    if (threadIdx.x == 0) {
        int run = 0;
        for (int b = 0; b < nb; b++) {
            int v = g_bsum[b];
            g_boff[b] = run;
            run += v;
        }
        g_rowptr[n] = run;
    }
}

__global__ void k_scan3(int n) {
    int i = blockIdx.x * 512 + threadIdx.x;
    if (i < n) g_rowptr[i] += g_boff[blockIdx.x];
}

// ---------------- CSR scatter ----------------
__global__ void k_scatter(const int* __restrict__ src, const int* __restrict__ dst, int e) {
    int i = blockIdx.x * blockDim.x + threadIdx.x;
    if (i < e) {
        int d = dst[i];
        int p = g_rowptr[d] + atomicAdd(&g_cursor[d], 1);
        g_col[p] = src[i];
    }
}

// ------------- HMMA GEMM: Y16[128-tile,128] = Xh @ W  (fp16 in/out, fp32 acc) -------------
__global__ void __launch_bounds__(256) k_mm(const __half* __restrict__ Xh,
                                            const __half* __restrict__ Wt,
                                            __half* __restrict__ Y, int n) {
    extern __shared__ __half sh[];
    __half* As = sh;                       // 128 x SSTR
    __half* Bs = sh + 128 * SSTR;          // 128 x SSTR  (Wt rows: [n][k])
    int tid = threadIdx.x;
    int base = blockIdx.x * 128;

    // ---- load Xh tile (already scaled fp16) ----
    const uint4* X4 = (const uint4*)Xh;
    #pragma unroll
    for (int i = 0; i < 8; i++) {
        int slot = i * 256 + tid;          // 2048 slots: row = slot/16, 8-half group j = slot%16
        int row = slot >> 4, j = slot & 15;
        int gr = base + row;
        uint4 v = make_uint4(0u, 0u, 0u, 0u);
        if (gr < n) v = X4[gr * 16 + j];
        *(uint4*)(As + row * SSTR + j * 8) = v;
    }
    // ---- load W^T fp16 ----
    const uint4* Wt4 = (const uint4*)Wt;
    #pragma unroll
    for (int i = 0; i < 8; i++) {
        int slot = i * 256 + tid;
        int row = slot >> 4, j = slot & 15;
        uint4 v = Wt4[slot];
        *(uint4*)(Bs + row * SSTR + j * 8) = v;
    }
    __syncthreads();

    int lane = tid & 31;
    int w = tid >> 5;
    int wm = (w & 3) * 32;     // row block
    int wn = (w >> 2) * 64;    // col block

    float acc[2][8][4];
    #pragma unroll
    for (int mi = 0; mi < 2; mi++)
        #pragma unroll
        for (int ni = 0; ni < 8; ni++)
            #pragma unroll
            for (int q = 0; q < 4; q++) acc[mi][ni][q] = 0.f;

    uint32_t a_base = smem_u32(As);
    uint32_t b_base = smem_u32(Bs);

    #pragma unroll
    for (int k0 = 0; k0 < 128; k0 += 16) {
        uint32_t af[2][4];
        #pragma unroll
        for (int mi = 0; mi < 2; mi++) {
            int row = wm + mi * 16 + (lane & 15);
            int col = k0 + (lane >> 4) * 8;
            ldsm_x4(af[mi], a_base + (uint32_t)(row * SSTR + col) * 2);
        }
        uint32_t bf[4][4];
        #pragma unroll
        for (int p = 0; p < 4; p++) {
            int row = wn + p * 16 + ((lane >> 4) & 1) * 8 + (lane & 7);
            int col = k0 + ((lane >> 3) & 1) * 8;
            ldsm_x4(bf[p], b_base + (uint32_t)(row * SSTR + col) * 2);
        }
        #pragma unroll
        for (int mi = 0; mi < 2; mi++)
            #pragma unroll
            for (int p = 0; p < 4; p++) {
                mma_f16(acc[mi][2 * p],     af[mi], bf[p][0], bf[p][1]);
                mma_f16(acc[mi][2 * p + 1], af[mi], bf[p][2], bf[p][3]);
            }
    }

    // ---- store fp16 messages ----
    __half2* Y2 = (__half2*)Y;
    #pragma unroll
    for (int mi = 0; mi < 2; mi++) {
        int r0 = base + wm + mi * 16 + (lane >> 2);
        int r1 = r0 + 8;
        #pragma unroll
        for (int ni = 0; ni < 8; ni++) {
            int col = wn + ni * 8 + (lane & 3) * 2;
            if (r0 < n) Y2[(r0 * 128 + col) >> 1] = __floats2half2_rn(acc[mi][ni][0], acc[mi][ni][1]);
            if (r1 < n) Y2[(r1 * 128 + col) >> 1] = __floats2half2_rn(acc[mi][ni][2], acc[mi][ni][3]);
        }
    }
}

// -------- aggregation core: fp16 message gather, fp32 accumulate --------
__device__ __forceinline__ float4 agg_gather(const __half* __restrict__ T, int s, int e2, int lane) {
    const uint2* T2 = (const uint2*)T;   // 4 halves per lane per row
    float4 a = make_float4(0.f, 0.f, 0.f, 0.f);
    int i = s;
    for (; i + 2 <= e2; i += 2) {
        int c0 = g_col[i], c1 = g_col[i + 1];
        uint2 v0 = T2[c0 * 32 + lane];
        uint2 v1 = T2[c1 * 32 + lane];
        float2 f0 = __half22float2(*(const __half2*)&v0.x);
        float2 f1 = __half22float2(*(const __half2*)&v0.y);
        float2 f2 = __half22float2(*(const __half2*)&v1.x);
        float2 f3 = __half22float2(*(const __half2*)&v1.y);
        a.x += f0.x + f2.x; a.y += f0.y + f2.y;
        a.z += f1.x + f3.x; a.w += f1.y + f3.y;
    }
    if (i < e2) {
        int c = g_col[i];
        uint2 v = T2[c * 32 + lane];
        float2 f0 = __half22float2(*(const __half2*)&v.x);
        float2 f1 = __half22float2(*(const __half2*)&v.y);
        a.x += f0.x; a.y += f0.y; a.z += f1.x; a.w += f1.y;
    }
    return a;
}

// ---- agg -> fp16 hidden pre-scaled by out_norm (layers 1,2) ----
__global__ void __launch_bounds__(256) k_agg_h(const __half* __restrict__ T,
                                               const float* __restrict__ bias,
                                               __half* __restrict__ Ho, int n) {
    int gw   = (blockIdx.x * 256 + threadIdx.x) >> 5;
    int lane = threadIdx.x & 31;
    if (gw >= n) return;
    float4 a = agg_gather(T, g_rowptr[gw], g_rowptr[gw + 1], lane);
    float sc = g_inn[gw];
    float on = g_outn[gw];
    float4 b = ((const float4*)bias)[lane];
    float rx = fmaxf(fmaf(a.x, sc, b.x), 0.f) * on;
    float ry = fmaxf(fmaf(a.y, sc, b.y), 0.f) * on;
    float rz = fmaxf(fmaf(a.z, sc, b.z), 0.f) * on;
    float rw = fmaxf(fmaf(a.w, sc, b.w), 0.f) * on;
    uint2 o;
    *(__half2*)&o.x = __floats2half2_rn(rx, ry);
    *(__half2*)&o.y = __floats2half2_rn(rz, rw);
    ((uint2*)Ho)[gw * 32 + lane] = o;
}

// ---- agg -> fp32 hidden (layer 3, feeds heads) ----
__global__ void __launch_bounds__(256) k_agg_f(const __half* __restrict__ T,
                                               const float* __restrict__ bias,
                                               float* __restrict__ Ho, int n) {
    int gw   = (blockIdx.x * 256 + threadIdx.x) >> 5;
    int lane = threadIdx.x & 31;
    if (gw >= n) return;
    float4 a = agg_gather(T, g_rowptr[gw], g_rowptr[gw + 1], lane);
    float sc = g_inn[gw];
    float4 b = ((const float4*)bias)[lane];
    float4 r;
    r.x = fmaxf(fmaf(a.x, sc, b.x), 0.f);
    r.y = fmaxf(fmaf(a.y, sc, b.y), 0.f);
    r.z = fmaxf(fmaf(a.z, sc, b.z), 0.f);
    r.w = fmaxf(fmaf(a.w, sc, b.w), 0.f);
    ((float4*)Ho)[gw * 32 + lane] = r;
}

// ---------------- column sums for mean over nodes ----------------
__global__ void k_colsum(const float* __restrict__ Hf, int n) {
    int t  = threadIdx.x;           // 128
    int r0 = blockIdx.x * 1024;
    int re = r0 + 1024; if (re > n) re = n;
    float sum = 0.f;
    for (int r = r0; r < re; r++) sum += Hf[r * HD + t];
    atomicAdd(&g_hg[t], sum);
}

// ---------------- seg_output ----------------
__global__ void k_seg(const float* __restrict__ Wp, const float* __restrict__ bp,
                      float* __restrict__ out, int n) {
    int c = threadIdx.x;
    if (c < 40) {
        float inv = 1.f / (float)n;
        float sum = bp[c];
        for (int k = 0; k < HD; k++) sum = fmaf(g_hg[k] * inv, Wp[c * HD + k], sum);
        out[c] = sum;
    }
}

// ---------------- CAM: out[c*n + node] = dot(Wp[c,:], H[node,:]) ----------------
__global__ void __launch_bounds__(256) k_cam(const float* __restrict__ Hf,
                                             const float* __restrict__ Wp,
                                             float* __restrict__ out, int n) {
    __shared__ float Ws[40 * HD];      // 20 KB
    __shared__ float Hs[64][33];       // 8.4 KB (k-chunked)
    int t = threadIdx.x;
    for (int i = t; i < 40 * HD; i += 256) Ws[i] = Wp[i];

    int base = blockIdx.x * 64;
    int ng = t & 31;
    int cg = t >> 5;
    int n0 = base + 2 * ng, n1 = n0 + 1;
    float acc0[5], acc1[5];
    #pragma unroll
    for (int j = 0; j < 5; j++) { acc0[j] = 0.f; acc1[j] = 0.f; }

    const float4* H4 = (const float4*)Hf;
    for (int k0 = 0; k0 < 128; k0 += 32) {
        __syncthreads();
        #pragma unroll
        for (int i = 0; i < 2; i++) {
            int idx = t + i * 256;
            int row = idx >> 3, q = idx & 7;
            int gr = base + row;
            float4 v = make_float4(0.f, 0.f, 0.f, 0.f);
            if (gr < n) v = H4[gr * 32 + (k0 >> 2) + q];
            Hs[row][q * 4 + 0] = v.x;
            Hs[row][q * 4 + 1] = v.y;
            Hs[row][q * 4 + 2] = v.z;
            Hs[row][q * 4 + 3] = v.w;
        }
        __syncthreads();
        #pragma unroll
        for (int kk = 0; kk < 32; kk++) {
            float a0 = Hs[2 * ng][kk];
            float a1 = Hs[2 * ng + 1][kk];
            #pragma unroll
            for (int j = 0; j < 5; j++) {
                float b = Ws[(5 * cg + j) * HD + k0 + kk];
                acc0[j] = fmaf(a0, b, acc0[j]);
                acc1[j] = fmaf(a1, b, acc1[j]);
            }
        }
    }
    #pragma unroll
    for (int j = 0; j < 5; j++) {
        int c = 5 * cg + j;
        if (n0 < n) out[c * n + n0] = acc0[j];
        if (n1 < n) out[c * n + n1] = acc1[j];
    }
}

// ---------------- launch ----------------
extern "C" void kernel_launch(void* const* d_in, const int* in_sizes, int n_in,
                              void* d_out, int out_size) {
    const float* features = (const float*)d_in[0];
    const float* W1 = (const float*)d_in[1];
    const float* b1 = (const float*)d_in[2];
    const float* W2 = (const float*)d_in[3];
    const float* b2 = (const float*)d_in[4];
    const float* W3 = (const float*)d_in[5];
    const float* b3 = (const float*)d_in[6];
    const float* Wp = (const float*)d_in[7];
    const float* bp = (const float*)d_in[8];
    const int*  src = (const int*)d_in[9];
    const int*  dst = (const int*)d_in[10];
    float* out = (float*)d_out;

    int n = in_sizes[0] / HD;          // 100000
    int e = in_sizes[9];               // 1600000

    int gn  = (n + 255) / 256;
    int ge  = (e + 255) / 256;
    int nb  = (n + 511) / 512;

    float *buf0;
    __half *h16a, *h16b, *m16, *wt1, *wt2, *wt3;
    cudaGetSymbolAddress((void**)&buf0, g_buf0);
    cudaGetSymbolAddress((void**)&h16a, g_h16a);
    cudaGetSymbolAddress((void**)&h16b, g_h16b);
    cudaGetSymbolAddress((void**)&m16,  g_m16);
    cudaGetSymbolAddress((void**)&wt1,  g_wt1);
    cudaGetSymbolAddress((void**)&wt2,  g_wt2);
    cudaGetSymbolAddress((void**)&wt3,  g_wt3);

    cudaFuncSetAttribute(k_mm, cudaFuncAttributeMaxDynamicSharedMemorySize, MM_SMEM);

    k_zero<<<gn, 256>>>(n);
    k_deg<<<ge, 256>>>(src, dst, e);
    k_norm<<<gn, 256>>>(n);
    k_prepw<<<(HD * HD + 255) / 256, 256>>>(W1, W2, W3);
    k_prepx<<<(n * 32 + 255) / 256, 256>>>(features, h16a, n);
    k_scan1<<<nb, 512>>>(n);
    k_scan2<<<1, 32>>>(nb, n);
    k_scan3<<<nb, 512>>>(n);
    k_scatter<<<ge, 256>>>(src, dst, e);

    int gt = (n + 127) / 128;   // GEMM tiles
    int ga = (n + 7) / 8;
    int gg = (n + 63) / 64;

    // layer 1
    k_mm<<<gt, 256, MM_SMEM>>>(h16a, wt1, m16, n);
    k_agg_h<<<ga, 256>>>(m16, b1, h16b, n);
    // layer 2
    k_mm<<<gt, 256, MM_SMEM>>>(h16b, wt2, m16, n);
    k_agg_h<<<ga, 256>>>(m16, b2, h16a, n);
    // layer 3
    k_mm<<<gt, 256, MM_SMEM>>>(h16a, wt3, m16, n);
    k_agg_f<<<ga, 256>>>(m16, b3, buf0, n);

    // heads
    k_colsum<<<(n + 1023) / 1024, 128>>>(buf0, n);
    k_seg<<<1, 64>>>(Wp, bp, out, n);
    k_cam<<<gg, 256>>>(buf0, Wp, out + 40, n);
}

// round 6
// speedup vs baseline: 1.8569x; 1.0664x over previous
#include <cuda_runtime.h>
#include <cuda_fp16.h>
#include <cuda_bf16.h>
#include <cstdint>

#define NMAX 100000
#define EMAX 1600000
#define HD   128

// ---------------- scratch (device globals; no allocation allowed) ----------------
__device__ __half g_h16a[NMAX * HD];    // fp16 hidden (pre-scaled by out_norm)
__device__ __half g_h16b[NMAX * HD];
__device__ __half g_m16[NMAX * HD];     // fp16 messages (GEMM output)
__device__ float g_outn[NMAX];
__device__ float g_inn[NMAX];
__device__ float g_hg[HD];
__device__ int   g_degout[NMAX];
__device__ int   g_degin[NMAX];
__device__ int   g_cursor[NMAX];
__device__ int   g_rowptr[NMAX + 1];
__device__ int   g_col[EMAX];
__device__ int   g_bsum[512];
__device__ __half g_wt1[HD * HD];       // W^T fp16: [n][k]
__device__ __half g_wt2[HD * HD];
__device__ __half g_wt3[HD * HD];

// ================= warp MMA helpers (baseline PTX, compiles on compute_103) ====
__device__ __forceinline__ uint32_t smem_u32(const void* p) {
    uint32_t a;
    asm("{ .reg .u64 t; cvta.to.shared.u64 t, %1; cvt.u32.u64 %0, t; }" : "=r"(a) : "l"(p));
    return a;
}
__device__ __forceinline__ void ldsm_x4(uint32_t* r, uint32_t addr) {
    asm volatile("ldmatrix.sync.aligned.m8n8.x4.shared.b16 {%0,%1,%2,%3}, [%4];"
                 : "=r"(r[0]), "=r"(r[1]), "=r"(r[2]), "=r"(r[3]) : "r"(addr));
}
__device__ __forceinline__ void mma_f16(float* d, const uint32_t* a, uint32_t b0, uint32_t b1) {
    asm volatile("mma.sync.aligned.m16n8k16.row.col.f32.f16.f16.f32 "
                 "{%0,%1,%2,%3}, {%4,%5,%6,%7}, {%8,%9}, {%0,%1,%2,%3};"
                 : "+f"(d[0]), "+f"(d[1]), "+f"(d[2]), "+f"(d[3])
                 : "r"(a[0]), "r"(a[1]), "r"(a[2]), "r"(a[3]), "r"(b0), "r"(b1));
}

#define SSTR 136   // smem row stride in halves (272B: 16B-aligned, conflict-free ldmatrix)
#define MM_SMEM (2 * 128 * SSTR * 2)

// ---------------- degrees ----------------
__global__ void k_deg(const int* __restrict__ src, const int* __restrict__ dst, int e) {
    int i = blockIdx.x * blockDim.x + threadIdx.x;
    if (i < e) {
        atomicAdd(&g_degout[src[i]], 1);
        atomicAdd(&g_degin[dst[i]], 1);
    }
}

__global__ void k_norm(int n) {
    int i = blockIdx.x * blockDim.x + threadIdx.x;
    if (i < n) {
        int a = g_degout[i]; if (a < 1) a = 1;
        int b = g_degin[i];  if (b < 1) b = 1;
        g_outn[i] = rsqrtf((float)a);
        g_inn[i]  = rsqrtf((float)b);
    }
}

// ------- fused prep: blocks [0,64) -> W^T fp16; blocks [64,..) -> X*out_norm fp16 -------
__global__ void k_prepall(const float* __restrict__ W1, const float* __restrict__ W2,
                          const float* __restrict__ W3, const float* __restrict__ X,
                          __half* __restrict__ Xh, int n) {
    if (blockIdx.x < 64) {
        int t = blockIdx.x * 256 + threadIdx.x;     // < 16384
        int k = t >> 7, c = t & 127;                // t = k*128 + c
        g_wt1[c * HD + k] = __float2half(W1[t]);
        g_wt2[c * HD + k] = __float2half(W2[t]);
        g_wt3[c * HD + k] = __float2half(W3[t]);
    } else {
        int i = (blockIdx.x - 64) * 256 + threadIdx.x;  // one float4 (4 cols) per thread
        if (i < n * 32) {
            float sv = g_outn[i >> 5];
            float4 a = ((const float4*)X)[i];
            __half2 h0 = __floats2half2_rn(a.x * sv, a.y * sv);
            __half2 h1 = __floats2half2_rn(a.z * sv, a.w * sv);
            ((__half2*)Xh)[i * 2]     = h0;
            ((__half2*)Xh)[i * 2 + 1] = h1;
        }
    }
}

// ---------------- exclusive scan of in-degrees -> row_ptr ----------------
__global__ void k_scan1(int n) {
    __shared__ int sh[512];
    int t = threadIdx.x;
    int i = blockIdx.x * 512 + t;
    int v = (i < n) ? g_degin[i] : 0;
    sh[t] = v;
    __syncthreads();
    #pragma unroll
    for (int off = 1; off < 512; off <<= 1) {
        int x = (t >= off) ? sh[t - off] : 0;
        __syncthreads();
        sh[t] += x;
        __syncthreads();
    }
    if (i < n) g_rowptr[i] = sh[t] - v;
    if (t == 511) g_bsum[blockIdx.x] = sh[511];
}

// scan2 folded in: each block serially prefixes the (<=196) block sums
__global__ void k_scan3(int nb, int n) {
    __shared__ int soff;
    if (threadIdx.x == 0) {
        int run = 0;
        for (int b = 0; b < blockIdx.x; b++) run += g_bsum[b];
        soff = run;
        if (blockIdx.x == nb - 1) g_rowptr[n] = run + g_bsum[nb - 1];
    }
    __syncthreads();
    int i = blockIdx.x * 512 + threadIdx.x;
    if (i < n) g_rowptr[i] += soff;
}

// ---------------- CSR scatter ----------------
__global__ void k_scatter(const int* __restrict__ src, const int* __restrict__ dst, int e) {
    int i = blockIdx.x * blockDim.x + threadIdx.x;
    if (i < e) {
        int d = dst[i];
        int p = g_rowptr[d] + atomicAdd(&g_cursor[d], 1);
        g_col[p] = src[i];
    }
}

// ------------- HMMA GEMM: Y16[128-tile,128] = Xh @ W  (fp16 in/out, fp32 acc) -------------
__global__ void __launch_bounds__(256) k_mm(const __half* __restrict__ Xh,
                                            const __half* __restrict__ Wt,
                                            __half* __restrict__ Y, int n) {
    extern __shared__ __half sh[];
    __half* As = sh;                       // 128 x SSTR
    __half* Bs = sh + 128 * SSTR;          // 128 x SSTR  (Wt rows: [n][k])
    int tid = threadIdx.x;
    int base = blockIdx.x * 128;

    // ---- load Xh tile (already scaled fp16) ----
    const uint4* X4 = (const uint4*)Xh;
    #pragma unroll
    for (int i = 0; i < 8; i++) {
        int slot = i * 256 + tid;          // 2048 slots: row = slot/16, 8-half group j = slot%16
        int row = slot >> 4, j = slot & 15;
        int gr = base + row;
        uint4 v = make_uint4(0u, 0u, 0u, 0u);
        if (gr < n) v = X4[gr * 16 + j];
        *(uint4*)(As + row * SSTR + j * 8) = v;
    }
    // ---- load W^T fp16 ----
    const uint4* Wt4 = (const uint4*)Wt;
    #pragma unroll
    for (int i = 0; i < 8; i++) {
        int slot = i * 256 + tid;
        int row = slot >> 4, j = slot & 15;
        uint4 v = Wt4[slot];
        *(uint4*)(Bs + row * SSTR + j * 8) = v;
    }
    __syncthreads();

    int lane = tid & 31;
    int w = tid >> 5;
    int wm = (w & 3) * 32;     // row block
    int wn = (w >> 2) * 64;    // col block

    float acc[2][8][4];
    #pragma unroll
    for (int mi = 0; mi < 2; mi++)
        #pragma unroll
        for (int ni = 0; ni < 8; ni++)
            #pragma unroll
            for (int q = 0; q < 4; q++) acc[mi][ni][q] = 0.f;

    uint32_t a_base = smem_u32(As);
    uint32_t b_base = smem_u32(Bs);

    #pragma unroll
    for (int k0 = 0; k0 < 128; k0 += 16) {
        uint32_t af[2][4];
        #pragma unroll
        for (int mi = 0; mi < 2; mi++) {
            int row = wm + mi * 16 + (lane & 15);
            int col = k0 + (lane >> 4) * 8;
            ldsm_x4(af[mi], a_base + (uint32_t)(row * SSTR + col) * 2);
        }
        uint32_t bf[4][4];
        #pragma unroll
        for (int p = 0; p < 4; p++) {
            int row = wn + p * 16 + ((lane >> 4) & 1) * 8 + (lane & 7);
            int col = k0 + ((lane >> 3) & 1) * 8;
            ldsm_x4(bf[p], b_base + (uint32_t)(row * SSTR + col) * 2);
        }
        #pragma unroll
        for (int mi = 0; mi < 2; mi++)
            #pragma unroll
            for (int p = 0; p < 4; p++) {
                mma_f16(acc[mi][2 * p],     af[mi], bf[p][0], bf[p][1]);
                mma_f16(acc[mi][2 * p + 1], af[mi], bf[p][2], bf[p][3]);
            }
    }

    // ---- store fp16 messages ----
    __half2* Y2 = (__half2*)Y;
    #pragma unroll
    for (int mi = 0; mi < 2; mi++) {
        int r0 = base + wm + mi * 16 + (lane >> 2);
        int r1 = r0 + 8;
        #pragma unroll
        for (int ni = 0; ni < 8; ni++) {
            int col = wn + ni * 8 + (lane & 3) * 2;
            if (r0 < n) Y2[(r0 * 128 + col) >> 1] = __floats2half2_rn(acc[mi][ni][0], acc[mi][ni][1]);
            if (r1 < n) Y2[(r1 * 128 + col) >> 1] = __floats2half2_rn(acc[mi][ni][2], acc[mi][ni][3]);
        }
    }
}

// -------- aggregation core: fp16 message gather, fp32 accumulate --------
__device__ __forceinline__ float4 agg_gather(const __half* __restrict__ T, int s, int e2, int lane) {
    const uint2* T2 = (const uint2*)T;   // 4 halves per lane per row
    float4 a = make_float4(0.f, 0.f, 0.f, 0.f);
    int i = s;
    for (; i + 4 <= e2; i += 4) {
        int c0 = g_col[i], c1 = g_col[i + 1], c2 = g_col[i + 2], c3 = g_col[i + 3];
        uint2 v0 = T2[c0 * 32 + lane];
        uint2 v1 = T2[c1 * 32 + lane];
        uint2 v2 = T2[c2 * 32 + lane];
        uint2 v3 = T2[c3 * 32 + lane];
        float2 f0 = __half22float2(*(const __half2*)&v0.x);
        float2 f1 = __half22float2(*(const __half2*)&v0.y);
        float2 f2 = __half22float2(*(const __half2*)&v1.x);
        float2 f3 = __half22float2(*(const __half2*)&v1.y);
        float2 f4 = __half22float2(*(const __half2*)&v2.x);
        float2 f5 = __half22float2(*(const __half2*)&v2.y);
        float2 f6 = __half22float2(*(const __half2*)&v3.x);
        float2 f7 = __half22float2(*(const __half2*)&v3.y);
        a.x += (f0.x + f2.x) + (f4.x + f6.x);
        a.y += (f0.y + f2.y) + (f4.y + f6.y);
        a.z += (f1.x + f3.x) + (f5.x + f7.x);
        a.w += (f1.y + f3.y) + (f5.y + f7.y);
    }
    for (; i < e2; i++) {
        int c = g_col[i];
        uint2 v = T2[c * 32 + lane];
        float2 f0 = __half22float2(*(const __half2*)&v.x);
        float2 f1 = __half22float2(*(const __half2*)&v.y);
        a.x += f0.x; a.y += f0.y; a.z += f1.x; a.w += f1.y;
    }
    return a;
}

// ---- agg -> fp16 hidden pre-scaled by out_norm (layers 1,2) ----
__global__ void __launch_bounds__(256) k_agg_h(const __half* __restrict__ T,
                                               const float* __restrict__ bias,
                                               __half* __restrict__ Ho, int n) {
    int gw   = (blockIdx.x * 256 + threadIdx.x) >> 5;
    int lane = threadIdx.x & 31;
    if (gw >= n) return;
    float4 a = agg_gather(T, g_rowptr[gw], g_rowptr[gw + 1], lane);
    float sc = g_inn[gw];
    float on = g_outn[gw];
    float4 b = ((const float4*)bias)[lane];
    float rx = fmaxf(fmaf(a.x, sc, b.x), 0.f) * on;
    float ry = fmaxf(fmaf(a.y, sc, b.y), 0.f) * on;
    float rz = fmaxf(fmaf(a.z, sc, b.z), 0.f) * on;
    float rw = fmaxf(fmaf(a.w, sc, b.w), 0.f) * on;
    uint2 o;
    *(__half2*)&o.x = __floats2half2_rn(rx, ry);
    *(__half2*)&o.y = __floats2half2_rn(rz, rw);
    ((uint2*)Ho)[gw * 32 + lane] = o;
}

// ---- agg -> fp16 hidden, no out_norm (layer 3, feeds heads) ----
__global__ void __launch_bounds__(256) k_agg_o(const __half* __restrict__ T,
                                               const float* __restrict__ bias,
                                               __half* __restrict__ Ho, int n) {
    int gw   = (blockIdx.x * 256 + threadIdx.x) >> 5;
    int lane = threadIdx.x & 31;
    if (gw >= n) return;
    float4 a = agg_gather(T, g_rowptr[gw], g_rowptr[gw + 1], lane);
    float sc = g_inn[gw];
    float4 b = ((const float4*)bias)[lane];
    float rx = fmaxf(fmaf(a.x, sc, b.x), 0.f);
    float ry = fmaxf(fmaf(a.y, sc, b.y), 0.f);
    float rz = fmaxf(fmaf(a.z, sc, b.z), 0.f);
    float rw = fmaxf(fmaf(a.w, sc, b.w), 0.f);
    uint2 o;
    *(__half2*)&o.x = __floats2half2_rn(rx, ry);
    *(__half2*)&o.y = __floats2half2_rn(rz, rw);
    ((uint2*)Ho)[gw * 32 + lane] = o;
}

// ---------------- column sums for mean over nodes (fp16 in, fp32 acc) ----------------
__global__ void k_colsum(const __half* __restrict__ Hh, int n) {
    int t  = threadIdx.x;           // 128
    int r0 = blockIdx.x * 1024;
    int re = r0 + 1024; if (re > n) re = n;
    float sum = 0.f;
    for (int r = r0; r < re; r++) sum += __half2float(Hh[r * HD + t]);
    atomicAdd(&g_hg[t], sum);
}

// ---------------- seg_output ----------------
__global__ void k_seg(const float* __restrict__ Wp, const float* __restrict__ bp,
                      float* __restrict__ out, int n) {
    int c = threadIdx.x;
    if (c < 40) {
        float inv = 1.f / (float)n;
        float sum = bp[c];
        for (int k = 0; k < HD; k++) sum = fmaf(g_hg[k] * inv, Wp[c * HD + k], sum);
        out[c] = sum;
    }
}

// ---------------- CAM: out[c*n + node] = dot(Wp[c,:], H[node,:])  (fp16 H) ----------------
__global__ void __launch_bounds__(256) k_cam(const __half* __restrict__ Hh,
                                             const float* __restrict__ Wp,
                                             float* __restrict__ out, int n) {
    __shared__ float Ws[40 * HD];      // 20 KB
    __shared__ float Hs[64][33];       // 8.4 KB (k-chunked)
    int t = threadIdx.x;
    for (int i = t; i < 40 * HD; i += 256) Ws[i] = Wp[i];

    int base = blockIdx.x * 64;
    int ng = t & 31;
    int cg = t >> 5;
    int n0 = base + 2 * ng, n1 = n0 + 1;
    float acc0[5], acc1[5];
    #pragma unroll
    for (int j = 0; j < 5; j++) { acc0[j] = 0.f; acc1[j] = 0.f; }

    const uint4* H4 = (const uint4*)Hh;   // 8 halves per uint4; 16 per row
    for (int k0 = 0; k0 < 128; k0 += 32) {
        __syncthreads();
        {
            int row = t >> 2, q = t & 3;   // 64 rows x 4 uint4 (32 halves) per chunk
            int gr = base + row;
            uint4 v = make_uint4(0u, 0u, 0u, 0u);
            if (gr < n) v = H4[gr * 16 + (k0 >> 3) + q];
            const __half2* hp = (const __half2*)&v;
            #pragma unroll
            for (int x = 0; x < 4; x++) {
                float2 f = __half22float2(hp[x]);
                Hs[row][q * 8 + x * 2]     = f.x;
                Hs[row][q * 8 + x * 2 + 1] = f.y;
            }
        }
        __syncthreads();
        #pragma unroll
        for (int kk = 0; kk < 32; kk++) {
            float a0 = Hs[2 * ng][kk];
            float a1 = Hs[2 * ng + 1][kk];
            #pragma unroll
            for (int j = 0; j < 5; j++) {
                float b = Ws[(5 * cg + j) * HD + k0 + kk];
                acc0[j] = fmaf(a0, b, acc0[j]);
                acc1[j] = fmaf(a1, b, acc1[j]);
            }
        }
    }
    #pragma unroll
    for (int j = 0; j < 5; j++) {
        int c = 5 * cg + j;
        if (n0 < n) out[c * n + n0] = acc0[j];
        if (n1 < n) out[c * n + n1] = acc1[j];
    }
}

// ---------------- launch ----------------
extern "C" void kernel_launch(void* const* d_in, const int* in_sizes, int n_in,
                              void* d_out, int out_size) {
    const float* features = (const float*)d_in[0];
    const float* W1 = (const float*)d_in[1];
    const float* b1 = (const float*)d_in[2];
    const float* W2 = (const float*)d_in[3];
    const float* b2 = (const float*)d_in[4];
    const float* W3 = (const float*)d_in[5];
    const float* b3 = (const float*)d_in[6];
    const float* Wp = (const float*)d_in[7];
    const float* bp = (const float*)d_in[8];
    const int*  src = (const int*)d_in[9];
    const int*  dst = (const int*)d_in[10];
    float* out = (float*)d_out;

    int n = in_sizes[0] / HD;          // 100000
    int e = in_sizes[9];               // 1600000

    int gn  = (n + 255) / 256;
    int ge  = (e + 255) / 256;
    int nb  = (n + 511) / 512;

    __half *h16a, *h16b, *m16, *wt1, *wt2, *wt3;
    void *degout, *degin, *cursor, *hg;
    cudaGetSymbolAddress((void**)&h16a, g_h16a);
    cudaGetSymbolAddress((void**)&h16b, g_h16b);
    cudaGetSymbolAddress((void**)&m16,  g_m16);
    cudaGetSymbolAddress((void**)&wt1,  g_wt1);
    cudaGetSymbolAddress((void**)&wt2,  g_wt2);
    cudaGetSymbolAddress((void**)&wt3,  g_wt3);
    cudaGetSymbolAddress(&degout, g_degout);
    cudaGetSymbolAddress(&degin,  g_degin);
    cudaGetSymbolAddress(&cursor, g_cursor);
    cudaGetSymbolAddress(&hg,     g_hg);

    cudaFuncSetAttribute(k_mm, cudaFuncAttributeMaxDynamicSharedMemorySize, MM_SMEM);

    cudaMemsetAsync(degout, 0, n * sizeof(int));
    cudaMemsetAsync(degin,  0, n * sizeof(int));
    cudaMemsetAsync(cursor, 0, n * sizeof(int));
    cudaMemsetAsync(hg,     0, HD * sizeof(float));

    int gt = (n + 127) / 128;   // GEMM tiles
    int ga = (n + 7) / 8;
    int gg = (n + 63) / 64;

    k_deg<<<ge, 256>>>(src, dst, e);                                   // 1
    k_norm<<<gn, 256>>>(n);                                            // 2
    k_prepall<<<64 + (n * 32 + 255) / 256, 256>>>(W1, W2, W3, features, h16a, n); // 3
    k_scan1<<<nb, 512>>>(n);                                           // 4
    k_scan3<<<nb, 512>>>(nb, n);                                       // 5
    k_mm<<<gt, 256, MM_SMEM>>>(h16a, wt1, m16, n);                     // 6 <- ncu profiles this
    k_scatter<<<ge, 256>>>(src, dst, e);                               // 7
    k_agg_h<<<ga, 256>>>(m16, b1, h16b, n);                            // 8
    k_mm<<<gt, 256, MM_SMEM>>>(h16b, wt2, m16, n);                     // 9
    k_agg_h<<<ga, 256>>>(m16, b2, h16a, n);                            // 10
    k_mm<<<gt, 256, MM_SMEM>>>(h16a, wt3, m16, n);                     // 11
    k_agg_o<<<ga, 256>>>(m16, b3, h16b, n);                            // 12

    // heads (fp16 H in h16b)
    k_colsum<<<(n + 1023) / 1024, 128>>>(h16b, n);                     // 13
    k_seg<<<1, 64>>>(Wp, bp, out, n);                                  // 14
    k_cam<<<gg, 256>>>(h16b, Wp, out + 40, n);                         // 15
}

// round 10
// speedup vs baseline: 1.8697x; 1.0069x over previous
#include <cuda_runtime.h>
#include <cuda_fp16.h>
#include <cuda_bf16.h>
#include <cstdint>

#define NMAX 100000
#define EMAX 1600000
#define HD   128

// ---------------- scratch (device globals; no allocation allowed) ----------------
__device__ __half g_h16a[NMAX * HD];    // fp16 hidden (pre-scaled by out_norm)
__device__ __half g_h16b[NMAX * HD];
__device__ __half g_m16[NMAX * HD];     // fp16 messages (GEMM output)
__device__ float g_hg[HD];
__device__ int   g_degout[NMAX];
__device__ int   g_degin[NMAX];
__device__ int   g_cursor[NMAX];
__device__ int   g_rowptr[NMAX + 1];
__device__ int   g_col[EMAX];
__device__ int   g_bsum[512];
__device__ __half g_wt1[HD * HD];       // W^T fp16: [n][k]
__device__ __half g_wt2[HD * HD];
__device__ __half g_wt3[HD * HD];

// ================= warp MMA helpers (baseline PTX, compiles on compute_103) ====
__device__ __forceinline__ uint32_t smem_u32(const void* p) {
    uint32_t a;
    asm("{ .reg .u64 t; cvta.to.shared.u64 t, %1; cvt.u32.u64 %0, t; }" : "=r"(a) : "l"(p));
    return a;
}
__device__ __forceinline__ void ldsm_x4(uint32_t* r, uint32_t addr) {
    asm volatile("ldmatrix.sync.aligned.m8n8.x4.shared.b16 {%0,%1,%2,%3}, [%4];"
                 : "=r"(r[0]), "=r"(r[1]), "=r"(r[2]), "=r"(r[3]) : "r"(addr));
}
__device__ __forceinline__ void mma_f16(float* d, const uint32_t* a, uint32_t b0, uint32_t b1) {
    asm volatile("mma.sync.aligned.m16n8k16.row.col.f32.f16.f16.f32 "
                 "{%0,%1,%2,%3}, {%4,%5,%6,%7}, {%8,%9}, {%0,%1,%2,%3};"
                 : "+f"(d[0]), "+f"(d[1]), "+f"(d[2]), "+f"(d[3])
                 : "r"(a[0]), "r"(a[1]), "r"(a[2]), "r"(a[3]), "r"(b0), "r"(b1));
}

#define SSTR 136   // smem row stride in halves (272B: 16B-aligned, conflict-free ldmatrix)
#define MM_SMEM (2 * 128 * SSTR * 2)

// ---------------- degrees (2 edges per thread) ----------------
__global__ void k_deg(const int* __restrict__ src, const int* __restrict__ dst, int e) {
    int i = blockIdx.x * blockDim.x + threadIdx.x;
    int eh = e >> 1;
    if (i < eh) {
        int2 s = ((const int2*)src)[i];
        int2 d = ((const int2*)dst)[i];
        atomicAdd(&g_degout[s.x], 1);
        atomicAdd(&g_degout[s.y], 1);
        atomicAdd(&g_degin[d.x], 1);
        atomicAdd(&g_degin[d.y], 1);
    }
    if (i == 0 && (e & 1)) {
        atomicAdd(&g_degout[src[e - 1]], 1);
        atomicAdd(&g_degin[dst[e - 1]], 1);
    }
}

// ------- fused prep: blocks [0,64) -> W^T fp16; blocks [64,..) -> X*out_norm fp16 -------
__global__ void k_prepall(const float* __restrict__ W1, const float* __restrict__ W2,
                          const float* __restrict__ W3, const float* __restrict__ X,
                          __half* __restrict__ Xh, int n) {
    if (blockIdx.x < 64) {
        int t = blockIdx.x * 256 + threadIdx.x;     // < 16384
        int k = t >> 7, c = t & 127;                // t = k*128 + c
        g_wt1[c * HD + k] = __float2half(W1[t]);
        g_wt2[c * HD + k] = __float2half(W2[t]);
        g_wt3[c * HD + k] = __float2half(W3[t]);
    } else {
        int i = (blockIdx.x - 64) * 256 + threadIdx.x;  // one float4 (4 cols) per thread
        if (i < n * 32) {
            int d = g_degout[i >> 5]; if (d < 1) d = 1;
            float sv = rsqrtf((float)d);
            float4 a = ((const float4*)X)[i];
            __half2 h0 = __floats2half2_rn(a.x * sv, a.y * sv);
            __half2 h1 = __floats2half2_rn(a.z * sv, a.w * sv);
            ((__half2*)Xh)[i * 2]     = h0;
            ((__half2*)Xh)[i * 2 + 1] = h1;
        }
    }
}

// ---------------- exclusive scan of in-degrees -> row_ptr ----------------
__global__ void k_scan1(int n) {
    __shared__ int sh[512];
    int t = threadIdx.x;
    int i = blockIdx.x * 512 + t;
    int v = (i < n) ? g_degin[i] : 0;
    sh[t] = v;
    __syncthreads();
    #pragma unroll
    for (int off = 1; off < 512; off <<= 1) {
        int x = (t >= off) ? sh[t - off] : 0;
        __syncthreads();
        sh[t] += x;
        __syncthreads();
    }
    if (i < n) g_rowptr[i] = sh[t] - v;
    if (t == 511) g_bsum[blockIdx.x] = sh[511];
}

// scan2 folded in: each block serially prefixes the (<=196) block sums; also seeds cursor
__global__ void k_scan3(int nb, int n) {
    __shared__ int soff;
    if (threadIdx.x == 0) {
        int run = 0;
        for (int b = 0; b < blockIdx.x; b++) run += g_bsum[b];
        soff = run;
        if (blockIdx.x == nb - 1) g_rowptr[n] = run + g_bsum[nb - 1];
    }
    __syncthreads();
    int i = blockIdx.x * 512 + threadIdx.x;
    if (i < n) {
        int v = g_rowptr[i] + soff;
        g_rowptr[i] = v;
        g_cursor[i] = v;         // scatter cursor starts at row base
    }
}

// ---------------- CSR scatter (cursor holds absolute positions) ----------------
__global__ void k_scatter(const int* __restrict__ src, const int* __restrict__ dst, int e) {
    int i = blockIdx.x * blockDim.x + threadIdx.x;
    if (i < e) {
        int p = atomicAdd(&g_cursor[dst[i]], 1);
        g_col[p] = src[i];
    }
}

// ------------- HMMA GEMM: Y16[128-tile,128] = Xh @ W  (fp16 in/out, fp32 acc) -------------
__global__ void __launch_bounds__(256) k_mm(const __half* __restrict__ Xh,
                                            const __half* __restrict__ Wt,
                                            __half* __restrict__ Y, int n) {
    extern __shared__ __half sh[];
    __half* As = sh;                       // 128 x SSTR
    __half* Bs = sh + 128 * SSTR;          // 128 x SSTR  (Wt rows: [n][k])
    int tid = threadIdx.x;
    int base = blockIdx.x * 128;

    // ---- load Xh tile (already scaled fp16) ----
    const uint4* X4 = (const uint4*)Xh;
    #pragma unroll
    for (int i = 0; i < 8; i++) {
        int slot = i * 256 + tid;          // 2048 slots: row = slot/16, 8-half group j = slot%16
        int row = slot >> 4, j = slot & 15;
        int gr = base + row;
        uint4 v = make_uint4(0u, 0u, 0u, 0u);
        if (gr < n) v = X4[gr * 16 + j];
        *(uint4*)(As + row * SSTR + j * 8) = v;
    }
    // ---- load W^T fp16 ----
    const uint4* Wt4 = (const uint4*)Wt;
    #pragma unroll
    for (int i = 0; i < 8; i++) {
        int slot = i * 256 + tid;
        int row = slot >> 4, j = slot & 15;
        uint4 v = Wt4[slot];
        *(uint4*)(Bs + row * SSTR + j * 8) = v;
    }
    __syncthreads();

    int lane = tid & 31;
    int w = tid >> 5;
    int wm = (w & 3) * 32;     // row block
    int wn = (w >> 2) * 64;    // col block

    float acc[2][8][4];
    #pragma unroll
    for (int mi = 0; mi < 2; mi++)
        #pragma unroll
        for (int ni = 0; ni < 8; ni++)
            #pragma unroll
            for (int q = 0; q < 4; q++) acc[mi][ni][q] = 0.f;

    uint32_t a_base = smem_u32(As);
    uint32_t b_base = smem_u32(Bs);

    #pragma unroll
    for (int k0 = 0; k0 < 128; k0 += 16) {
        uint32_t af[2][4];
        #pragma unroll
        for (int mi = 0; mi < 2; mi++) {
            int row = wm + mi * 16 + (lane & 15);
            int col = k0 + (lane >> 4) * 8;
            ldsm_x4(af[mi], a_base + (uint32_t)(row * SSTR + col) * 2);
        }
        uint32_t bf[4][4];
        #pragma unroll
        for (int p = 0; p < 4; p++) {
            int row = wn + p * 16 + ((lane >> 4) & 1) * 8 + (lane & 7);
            int col = k0 + ((lane >> 3) & 1) * 8;
            ldsm_x4(bf[p], b_base + (uint32_t)(row * SSTR + col) * 2);
        }
        #pragma unroll
        for (int mi = 0; mi < 2; mi++)
            #pragma unroll
            for (int p = 0; p < 4; p++) {
                mma_f16(acc[mi][2 * p],     af[mi], bf[p][0], bf[p][1]);
                mma_f16(acc[mi][2 * p + 1], af[mi], bf[p][2], bf[p][3]);
            }
    }

    // ---- store fp16 messages ----
    __half2* Y2 = (__half2*)Y;
    #pragma unroll
    for (int mi = 0; mi < 2; mi++) {
        int r0 = base + wm + mi * 16 + (lane >> 2);
        int r1 = r0 + 8;
        #pragma unroll
        for (int ni = 0; ni < 8; ni++) {
            int col = wn + ni * 8 + (lane & 3) * 2;
            if (r0 < n) Y2[(r0 * 128 + col) >> 1] = __floats2half2_rn(acc[mi][ni][0], acc[mi][ni][1]);
            if (r1 < n) Y2[(r1 * 128 + col) >> 1] = __floats2half2_rn(acc[mi][ni][2], acc[mi][ni][3]);
        }
    }
}

// -------- aggregation core: fp16 message gather, fp32 accumulate --------
__device__ __forceinline__ float4 agg_gather(const __half* __restrict__ T, int s, int e2, int lane) {
    const uint2* T2 = (const uint2*)T;   // 4 halves per lane per row
    float4 a = make_float4(0.f, 0.f, 0.f, 0.f);
    int i = s;
    for (; i + 4 <= e2; i += 4) {
        int c0 = g_col[i], c1 = g_col[i + 1], c2 = g_col[i + 2], c3 = g_col[i + 3];
        uint2 v0 = T2[c0 * 32 + lane];
        uint2 v1 = T2[c1 * 32 + lane];
        uint2 v2 = T2[c2 * 32 + lane];
        uint2 v3 = T2[c3 * 32 + lane];
        float2 f0 = __half22float2(*(const __half2*)&v0.x);
        float2 f1 = __half22float2(*(const __half2*)&v0.y);
        float2 f2 = __half22float2(*(const __half2*)&v1.x);
        float2 f3 = __half22float2(*(const __half2*)&v1.y);
        float2 f4 = __half22float2(*(const __half2*)&v2.x);
        float2 f5 = __half22float2(*(const __half2*)&v2.y);
        float2 f6 = __half22float2(*(const __half2*)&v3.x);
        float2 f7 = __half22float2(*(const __half2*)&v3.y);
        a.x += (f0.x + f2.x) + (f4.x + f6.x);
        a.y += (f0.y + f2.y) + (f4.y + f6.y);
        a.z += (f1.x + f3.x) + (f5.x + f7.x);
        a.w += (f1.y + f3.y) + (f5.y + f7.y);
    }
    for (; i < e2; i++) {
        int c = g_col[i];
        uint2 v = T2[c * 32 + lane];
        float2 f0 = __half22float2(*(const __half2*)&v.x);
        float2 f1 = __half22float2(*(const __half2*)&v.y);
        a.x += f0.x; a.y += f0.y; a.z += f1.x; a.w += f1.y;
    }
    return a;
}

// ---- agg -> fp16 hidden pre-scaled by out_norm (layers 1,2); norms inline ----
__global__ void __launch_bounds__(256) k_agg_h(const __half* __restrict__ T,
                                               const float* __restrict__ bias,
                                               __half* __restrict__ Ho, int n) {
    int gw   = (blockIdx.x * 256 + threadIdx.x) >> 5;
    int lane = threadIdx.x & 31;
    if (gw >= n) return;
    float4 a = agg_gather(T, g_rowptr[gw], g_rowptr[gw + 1], lane);
    int dI = g_degin[gw];  if (dI < 1) dI = 1;
    int dO = g_degout[gw]; if (dO < 1) dO = 1;
    float sc = rsqrtf((float)dI);
    float on = rsqrtf((float)dO);
    float4 b = ((const float4*)bias)[lane];
    float rx = fmaxf(fmaf(a.x, sc, b.x), 0.f) * on;
    float ry = fmaxf(fmaf(a.y, sc, b.y), 0.f) * on;
    float rz = fmaxf(fmaf(a.z, sc, b.z), 0.f) * on;
    float rw = fmaxf(fmaf(a.w, sc, b.w), 0.f) * on;
    uint2 o;
    *(__half2*)&o.x = __floats2half2_rn(rx, ry);
    *(__half2*)&o.y = __floats2half2_rn(rz, rw);
    ((uint2*)Ho)[gw * 32 + lane] = o;
}

// ---- agg -> fp16 hidden, no out_norm (layer 3, feeds heads) ----
__global__ void __launch_bounds__(256) k_agg_o(const __half* __restrict__ T,
                                               const float* __restrict__ bias,
                                               __half* __restrict__ Ho, int n) {
    int gw   = (blockIdx.x * 256 + threadIdx.x) >> 5;
    int lane = threadIdx.x & 31;
    if (gw >= n) return;
    float4 a = agg_gather(T, g_rowptr[gw], g_rowptr[gw + 1], lane);
    int dI = g_degin[gw]; if (dI < 1) dI = 1;
    float sc = rsqrtf((float)dI);
    float4 b = ((const float4*)bias)[lane];
    float rx = fmaxf(fmaf(a.x, sc, b.x), 0.f);
    float ry = fmaxf(fmaf(a.y, sc, b.y), 0.f);
    float rz = fmaxf(fmaf(a.z, sc, b.z), 0.f);
    float rw = fmaxf(fmaf(a.w, sc, b.w), 0.f);
    uint2 o;
    *(__half2*)&o.x = __floats2half2_rn(rx, ry);
    *(__half2*)&o.y = __floats2half2_rn(rz, rw);
    ((uint2*)Ho)[gw * 32 + lane] = o;
}

// ---------------- column sums for mean over nodes (fp16 in, fp32 acc) ----------------
__global__ void k_colsum(const __half* __restrict__ Hh, int n) {
    int t  = threadIdx.x;           // 128
    int r0 = blockIdx.x * 1024;
    int re = r0 + 1024; if (re > n) re = n;
    float sum = 0.f;
    for (int r = r0; r < re; r++) sum += __half2float(Hh[r * HD + t]);
    atomicAdd(&g_hg[t], sum);
}

// ---------------- seg_output ----------------
__global__ void k_seg(const float* __restrict__ Wp, const float* __restrict__ bp,
                      float* __restrict__ out, int n) {
    int c = threadIdx.x;
    if (c < 40) {
        float inv = 1.f / (float)n;
        float sum = bp[c];
        for (int k = 0; k < HD; k++) sum = fmaf(g_hg[k] * inv, Wp[c * HD + k], sum);
        out[c] = sum;
    }
}

// ---------------- CAM: out[c*n + node] = dot(Wp[c,:], H[node,:])  (fp16 H) ----------------
__global__ void __launch_bounds__(256) k_cam(const __half* __restrict__ Hh,
                                             const float* __restrict__ Wp,
                                             float* __restrict__ out, int n) {
    __shared__ float Ws[40 * HD];      // 20 KB
    __shared__ float Hs[64][33];       // 8.4 KB (k-chunked)
    int t = threadIdx.x;
    for (int i = t; i < 40 * HD; i += 256) Ws[i] = Wp[i];

    int base = blockIdx.x * 64;
    int ng = t & 31;
    int cg = t >> 5;
    int n0 = base + 2 * ng, n1 = n0 + 1;
    float acc0[5], acc1[5];
    #pragma unroll
    for (int j = 0; j < 5; j++) { acc0[j] = 0.f; acc1[j] = 0.f; }

    const uint4* H4 = (const uint4*)Hh;   // 8 halves per uint4; 16 per row
    for (int k0 = 0; k0 < 128; k0 += 32) {
        __syncthreads();
        {
            int row = t >> 2, q = t & 3;   // 64 rows x 4 uint4 (32 halves) per chunk
            int gr = base + row;
            uint4 v = make_uint4(0u, 0u, 0u, 0u);
            if (gr < n) v = H4[gr * 16 + (k0 >> 3) + q];
            const __half2* hp = (const __half2*)&v;
            #pragma unroll
            for (int x = 0; x < 4; x++) {
                float2 f = __half22float2(hp[x]);
                Hs[row][q * 8 + x * 2]     = f.x;
                Hs[row][q * 8 + x * 2 + 1] = f.y;
            }
        }
        __syncthreads();
        #pragma unroll
        for (int kk = 0; kk < 32; kk++) {
            float a0 = Hs[2 * ng][kk];
            float a1 = Hs[2 * ng + 1][kk];
            #pragma unroll
            for (int j = 0; j < 5; j++) {
                float b = Ws[(5 * cg + j) * HD + k0 + kk];
                acc0[j] = fmaf(a0, b, acc0[j]);
                acc1[j] = fmaf(a1, b, acc1[j]);
            }
        }
    }
    #pragma unroll
    for (int j = 0; j < 5; j++) {
        int c = 5 * cg + j;
        if (n0 < n) out[c * n + n0] = acc0[j];
        if (n1 < n) out[c * n + n1] = acc1[j];
    }
}

// ---------------- launch ----------------
extern "C" void kernel_launch(void* const* d_in, const int* in_sizes, int n_in,
                              void* d_out, int out_size) {
    const float* features = (const float*)d_in[0];
    const float* W1 = (const float*)d_in[1];
    const float* b1 = (const float*)d_in[2];
    const float* W2 = (const float*)d_in[3];
    const float* b2 = (const float*)d_in[4];
    const float* W3 = (const float*)d_in[5];
    const float* b3 = (const float*)d_in[6];
    const float* Wp = (const float*)d_in[7];
    const float* bp = (const float*)d_in[8];
    const int*  src = (const int*)d_in[9];
    const int*  dst = (const int*)d_in[10];
    float* out = (float*)d_out;

    int n = in_sizes[0] / HD;          // 100000
    int e = in_sizes[9];               // 1600000

    int ge  = (e + 255) / 256;
    int nb  = (n + 511) / 512;

    __half *h16a, *h16b, *m16, *wt1, *wt2, *wt3;
    void *degout, *degin, *hg;
    cudaGetSymbolAddress((void**)&h16a, g_h16a);
    cudaGetSymbolAddress((void**)&h16b, g_h16b);
    cudaGetSymbolAddress((void**)&m16,  g_m16);
    cudaGetSymbolAddress((void**)&wt1,  g_wt1);
    cudaGetSymbolAddress((void**)&wt2,  g_wt2);
    cudaGetSymbolAddress((void**)&wt3,  g_wt3);
    cudaGetSymbolAddress(&degout, g_degout);
    cudaGetSymbolAddress(&degin,  g_degin);
    cudaGetSymbolAddress(&hg,     g_hg);

    cudaFuncSetAttribute(k_mm, cudaFuncAttributeMaxDynamicSharedMemorySize, MM_SMEM);

    cudaMemsetAsync(degout, 0, n * sizeof(int));
    cudaMemsetAsync(degin,  0, n * sizeof(int));
    cudaMemsetAsync(hg,     0, HD * sizeof(float));

    int gt = (n + 127) / 128;   // GEMM tiles
    int ga = (n + 7) / 8;
    int gg = (n + 63) / 64;

    k_deg<<<(e / 2 + 255) / 256, 256>>>(src, dst, e);                           // 1
    k_prepall<<<64 + (n * 32 + 255) / 256, 256>>>(W1, W2, W3, features, h16a, n); // 2
    k_scan1<<<nb, 512>>>(n);                                                    // 3
    k_mm<<<gt, 256, MM_SMEM>>>(h16a, wt1, m16, n);                              // 4 <- ncu profiles this
    k_scan3<<<nb, 512>>>(nb, n);                                                // 5
    k_scatter<<<ge, 256>>>(src, dst, e);                                        // 6
    k_agg_h<<<ga, 256>>>(m16, b1, h16b, n);                                     // 7
    k_mm<<<gt, 256, MM_SMEM>>>(h16b, wt2, m16, n);                              // 8
    k_agg_h<<<ga, 256>>>(m16, b2, h16a, n);                                     // 9
    k_mm<<<gt, 256, MM_SMEM>>>(h16a, wt3, m16, n);                              // 10
    k_agg_o<<<ga, 256>>>(m16, b3, h16b, n);                                     // 11

    // heads (fp16 H in h16b)
    k_colsum<<<(n + 1023) / 1024, 128>>>(h16b, n);                              // 12
    k_seg<<<1, 64>>>(Wp, bp, out, n);                                           // 13
    k_cam<<<gg, 256>>>(h16b, Wp, out + 40, n);                                  // 14
}

// round 11
// speedup vs baseline: 2.1732x; 1.1623x over previous
#include <cuda_runtime.h>
#include <cuda_fp16.h>
#include <cuda_bf16.h>
#include <cstdint>

#define NMAX 100000
#define EMAX 1600000
#define HD   128

// ---------------- scratch (device globals; no allocation allowed) ----------------
__device__ __half g_h16a[NMAX * HD];    // fp16 hidden (pre-scaled by out_norm)
__device__ __half g_h16b[NMAX * HD];
__device__ __half g_m16[NMAX * HD];     // fp16 messages (GEMM output)
__device__ float g_hg[HD];
__device__ int   g_degout[NMAX];
__device__ int   g_degin[NMAX];
__device__ int   g_cursor[NMAX];
__device__ int   g_rowptr[NMAX + 1];
__device__ int   g_col[EMAX];
__device__ int   g_bsum[512];
__device__ __half g_wt1[HD * HD];       // W^T fp16: [n][k]
__device__ __half g_wt2[HD * HD];
__device__ __half g_wt3[HD * HD];
__device__ __half g_wpt[64 * HD];       // Wp fp16 [64][128], rows 40..63 zero

// ================= warp MMA helpers (baseline PTX, compiles on compute_103) ====
__device__ __forceinline__ uint32_t smem_u32(const void* p) {
    uint32_t a;
    asm("{ .reg .u64 t; cvta.to.shared.u64 t, %1; cvt.u32.u64 %0, t; }" : "=r"(a) : "l"(p));
    return a;
}
__device__ __forceinline__ void ldsm_x4(uint32_t* r, uint32_t addr) {
    asm volatile("ldmatrix.sync.aligned.m8n8.x4.shared.b16 {%0,%1,%2,%3}, [%4];"
                 : "=r"(r[0]), "=r"(r[1]), "=r"(r[2]), "=r"(r[3]) : "r"(addr));
}
__device__ __forceinline__ void mma_f16(float* d, const uint32_t* a, uint32_t b0, uint32_t b1) {
    asm volatile("mma.sync.aligned.m16n8k16.row.col.f32.f16.f16.f32 "
                 "{%0,%1,%2,%3}, {%4,%5,%6,%7}, {%8,%9}, {%0,%1,%2,%3};"
                 : "+f"(d[0]), "+f"(d[1]), "+f"(d[2]), "+f"(d[3])
                 : "r"(a[0]), "r"(a[1]), "r"(a[2]), "r"(a[3]), "r"(b0), "r"(b1));
}

#define SSTR 136   // smem row stride in halves (272B: 16B-aligned, conflict-free ldmatrix)
#define MM_SMEM (2 * 128 * SSTR * 2)
#define CAM_SMEM (192 * SSTR * 2)   // 128-row H tile + 64-row Wp tile (fp32 Ts overlays)

// ---------------- degrees (2 edges per thread) ----------------
__global__ void k_deg(const int* __restrict__ src, const int* __restrict__ dst, int e) {
    int i = blockIdx.x * blockDim.x + threadIdx.x;
    int eh = e >> 1;
    if (i < eh) {
        int2 s = ((const int2*)src)[i];
        int2 d = ((const int2*)dst)[i];
        atomicAdd(&g_degout[s.x], 1);
        atomicAdd(&g_degout[s.y], 1);
        atomicAdd(&g_degin[d.x], 1);
        atomicAdd(&g_degin[d.y], 1);
    }
    if (i == 0 && (e & 1)) {
        atomicAdd(&g_degout[src[e - 1]], 1);
        atomicAdd(&g_degin[dst[e - 1]], 1);
    }
}

// ------- fused prep: [0,64) W^T fp16; [64,96) Wp fp16 padded; [96,..) X*out_norm fp16 -----
__global__ void k_prepall(const float* __restrict__ W1, const float* __restrict__ W2,
                          const float* __restrict__ W3, const float* __restrict__ Wp,
                          const float* __restrict__ X, __half* __restrict__ Xh, int n) {
    if (blockIdx.x < 64) {
        int t = blockIdx.x * 256 + threadIdx.x;     // < 16384
        int k = t >> 7, c = t & 127;                // t = k*128 + c
        g_wt1[c * HD + k] = __float2half(W1[t]);
        g_wt2[c * HD + k] = __float2half(W2[t]);
        g_wt3[c * HD + k] = __float2half(W3[t]);
    } else if (blockIdx.x < 96) {
        int t = (blockIdx.x - 64) * 256 + threadIdx.x;  // < 8192 = 64*128
        int r = t >> 7;
        g_wpt[t] = (r < 40) ? __float2half(Wp[t]) : __float2half(0.f);
    } else {
        int i = (blockIdx.x - 96) * 256 + threadIdx.x;  // one float4 (4 cols) per thread
        if (i < n * 32) {
            int d = g_degout[i >> 5]; if (d < 1) d = 1;
            float sv = rsqrtf((float)d);
            float4 a = ((const float4*)X)[i];
            __half2 h0 = __floats2half2_rn(a.x * sv, a.y * sv);
            __half2 h1 = __floats2half2_rn(a.z * sv, a.w * sv);
            ((__half2*)Xh)[i * 2]     = h0;
            ((__half2*)Xh)[i * 2 + 1] = h1;
        }
    }
}

// ---------------- exclusive scan of in-degrees -> row_ptr ----------------
__global__ void k_scan1(int n) {
    __shared__ int sh[512];
    int t = threadIdx.x;
    int i = blockIdx.x * 512 + t;
    int v = (i < n) ? g_degin[i] : 0;
    sh[t] = v;
    __syncthreads();
    #pragma unroll
    for (int off = 1; off < 512; off <<= 1) {
        int x = (t >= off) ? sh[t - off] : 0;
        __syncthreads();
        sh[t] += x;
        __syncthreads();
    }
    if (i < n) g_rowptr[i] = sh[t] - v;
    if (t == 511) g_bsum[blockIdx.x] = sh[511];
}

// scan2 folded in: each block serially prefixes the (<=196) block sums; also seeds cursor
__global__ void k_scan3(int nb, int n) {
    __shared__ int soff;
    if (threadIdx.x == 0) {
        int run = 0;
        for (int b = 0; b < blockIdx.x; b++) run += g_bsum[b];
        soff = run;
        if (blockIdx.x == nb - 1) g_rowptr[n] = run + g_bsum[nb - 1];
    }
    __syncthreads();
    int i = blockIdx.x * 512 + threadIdx.x;
    if (i < n) {
        int v = g_rowptr[i] + soff;
        g_rowptr[i] = v;
        g_cursor[i] = v;         // scatter cursor starts at row base
    }
}

// ---------------- CSR scatter (cursor holds absolute positions) ----------------
__global__ void k_scatter(const int* __restrict__ src, const int* __restrict__ dst, int e) {
    int i = blockIdx.x * blockDim.x + threadIdx.x;
    if (i < e) {
        int p = atomicAdd(&g_cursor[dst[i]], 1);
        g_col[p] = src[i];
    }
}

// ------------- HMMA GEMM: Y16[128-tile,128] = Xh @ W  (fp16 in/out, fp32 acc) -------------
__global__ void __launch_bounds__(256) k_mm(const __half* __restrict__ Xh,
                                            const __half* __restrict__ Wt,
                                            __half* __restrict__ Y, int n) {
    extern __shared__ __half sh[];
    __half* As = sh;                       // 128 x SSTR
    __half* Bs = sh + 128 * SSTR;          // 128 x SSTR  (Wt rows: [n][k])
    int tid = threadIdx.x;
    int base = blockIdx.x * 128;

    // ---- load Xh tile (already scaled fp16) ----
    const uint4* X4 = (const uint4*)Xh;
    #pragma unroll
    for (int i = 0; i < 8; i++) {
        int slot = i * 256 + tid;          // 2048 slots: row = slot/16, 8-half group j = slot%16
        int row = slot >> 4, j = slot & 15;
        int gr = base + row;
        uint4 v = make_uint4(0u, 0u, 0u, 0u);
        if (gr < n) v = X4[gr * 16 + j];
        *(uint4*)(As + row * SSTR + j * 8) = v;
    }
    // ---- load W^T fp16 ----
    const uint4* Wt4 = (const uint4*)Wt;
    #pragma unroll
    for (int i = 0; i < 8; i++) {
        int slot = i * 256 + tid;
        int row = slot >> 4, j = slot & 15;
        uint4 v = Wt4[slot];
        *(uint4*)(Bs + row * SSTR + j * 8) = v;
    }
    __syncthreads();

    int lane = tid & 31;
    int w = tid >> 5;
    int wm = (w & 3) * 32;     // row block
    int wn = (w >> 2) * 64;    // col block

    float acc[2][8][4];
    #pragma unroll
    for (int mi = 0; mi < 2; mi++)
        #pragma unroll
        for (int ni = 0; ni < 8; ni++)
            #pragma unroll
            for (int q = 0; q < 4; q++) acc[mi][ni][q] = 0.f;

    uint32_t a_base = smem_u32(As);
    uint32_t b_base = smem_u32(Bs);

    #pragma unroll
    for (int k0 = 0; k0 < 128; k0 += 16) {
        uint32_t af[2][4];
        #pragma unroll
        for (int mi = 0; mi < 2; mi++) {
            int row = wm + mi * 16 + (lane & 15);
            int col = k0 + (lane >> 4) * 8;
            ldsm_x4(af[mi], a_base + (uint32_t)(row * SSTR + col) * 2);
        }
        uint32_t bf[4][4];
        #pragma unroll
        for (int p = 0; p < 4; p++) {
            int row = wn + p * 16 + ((lane >> 4) & 1) * 8 + (lane & 7);
            int col = k0 + ((lane >> 3) & 1) * 8;
            ldsm_x4(bf[p], b_base + (uint32_t)(row * SSTR + col) * 2);
        }
        #pragma unroll
        for (int mi = 0; mi < 2; mi++)
            #pragma unroll
            for (int p = 0; p < 4; p++) {
                mma_f16(acc[mi][2 * p],     af[mi], bf[p][0], bf[p][1]);
                mma_f16(acc[mi][2 * p + 1], af[mi], bf[p][2], bf[p][3]);
            }
    }

    // ---- store fp16 messages ----
    __half2* Y2 = (__half2*)Y;
    #pragma unroll
    for (int mi = 0; mi < 2; mi++) {
        int r0 = base + wm + mi * 16 + (lane >> 2);
        int r1 = r0 + 8;
        #pragma unroll
        for (int ni = 0; ni < 8; ni++) {
            int col = wn + ni * 8 + (lane & 3) * 2;
            if (r0 < n) Y2[(r0 * 128 + col) >> 1] = __floats2half2_rn(acc[mi][ni][0], acc[mi][ni][1]);
            if (r1 < n) Y2[(r1 * 128 + col) >> 1] = __floats2half2_rn(acc[mi][ni][2], acc[mi][ni][3]);
        }
    }
}

// -------- aggregation core: fp16 message gather, fp32 accumulate --------
__device__ __forceinline__ float4 agg_gather(const __half* __restrict__ T, int s, int e2, int lane) {
    const uint2* T2 = (const uint2*)T;   // 4 halves per lane per row
    float4 a = make_float4(0.f, 0.f, 0.f, 0.f);
    int i = s;
    for (; i + 4 <= e2; i += 4) {
        int c0 = g_col[i], c1 = g_col[i + 1], c2 = g_col[i + 2], c3 = g_col[i + 3];
        uint2 v0 = T2[c0 * 32 + lane];
        uint2 v1 = T2[c1 * 32 + lane];
        uint2 v2 = T2[c2 * 32 + lane];
        uint2 v3 = T2[c3 * 32 + lane];
        float2 f0 = __half22float2(*(const __half2*)&v0.x);
        float2 f1 = __half22float2(*(const __half2*)&v0.y);
        float2 f2 = __half22float2(*(const __half2*)&v1.x);
        float2 f3 = __half22float2(*(const __half2*)&v1.y);
        float2 f4 = __half22float2(*(const __half2*)&v2.x);
        float2 f5 = __half22float2(*(const __half2*)&v2.y);
        float2 f6 = __half22float2(*(const __half2*)&v3.x);
        float2 f7 = __half22float2(*(const __half2*)&v3.y);
        a.x += (f0.x + f2.x) + (f4.x + f6.x);
        a.y += (f0.y + f2.y) + (f4.y + f6.y);
        a.z += (f1.x + f3.x) + (f5.x + f7.x);
        a.w += (f1.y + f3.y) + (f5.y + f7.y);
    }
    for (; i < e2; i++) {
        int c = g_col[i];
        uint2 v = T2[c * 32 + lane];
        float2 f0 = __half22float2(*(const __half2*)&v.x);
        float2 f1 = __half22float2(*(const __half2*)&v.y);
        a.x += f0.x; a.y += f0.y; a.z += f1.x; a.w += f1.y;
    }
    return a;
}

// ---- agg -> fp16 hidden pre-scaled by out_norm (layers 1,2); norms inline ----
__global__ void __launch_bounds__(256) k_agg_h(const __half* __restrict__ T,
                                               const float* __restrict__ bias,
                                               __half* __restrict__ Ho, int n) {
    int gw   = (blockIdx.x * 256 + threadIdx.x) >> 5;
    int lane = threadIdx.x & 31;
    if (gw >= n) return;
    float4 a = agg_gather(T, g_rowptr[gw], g_rowptr[gw + 1], lane);
    int dI = g_degin[gw];  if (dI < 1) dI = 1;
    int dO = g_degout[gw]; if (dO < 1) dO = 1;
    float sc = rsqrtf((float)dI);
    float on = rsqrtf((float)dO);
    float4 b = ((const float4*)bias)[lane];
    float rx = fmaxf(fmaf(a.x, sc, b.x), 0.f) * on;
    float ry = fmaxf(fmaf(a.y, sc, b.y), 0.f) * on;
    float rz = fmaxf(fmaf(a.z, sc, b.z), 0.f) * on;
    float rw = fmaxf(fmaf(a.w, sc, b.w), 0.f) * on;
    uint2 o;
    *(__half2*)&o.x = __floats2half2_rn(rx, ry);
    *(__half2*)&o.y = __floats2half2_rn(rz, rw);
    ((uint2*)Ho)[gw * 32 + lane] = o;
}

// ---- agg -> fp16 hidden, no out_norm (layer 3, feeds heads) ----
__global__ void __launch_bounds__(256) k_agg_o(const __half* __restrict__ T,
                                               const float* __restrict__ bias,
                                               __half* __restrict__ Ho, int n) {
    int gw   = (blockIdx.x * 256 + threadIdx.x) >> 5;
    int lane = threadIdx.x & 31;
    if (gw >= n) return;
    float4 a = agg_gather(T, g_rowptr[gw], g_rowptr[gw + 1], lane);
    int dI = g_degin[gw]; if (dI < 1) dI = 1;
    float sc = rsqrtf((float)dI);
    float4 b = ((const float4*)bias)[lane];
    float rx = fmaxf(fmaf(a.x, sc, b.x), 0.f);
    float ry = fmaxf(fmaf(a.y, sc, b.y), 0.f);
    float rz = fmaxf(fmaf(a.z, sc, b.z), 0.f);
    float rw = fmaxf(fmaf(a.w, sc, b.w), 0.f);
    uint2 o;
    *(__half2*)&o.x = __floats2half2_rn(rx, ry);
    *(__half2*)&o.y = __floats2half2_rn(rz, rw);
    ((uint2*)Ho)[gw * 32 + lane] = o;
}

// ---------------- seg_output ----------------
__global__ void k_seg(const float* __restrict__ Wp, const float* __restrict__ bp,
                      float* __restrict__ out, int n) {
    int c = threadIdx.x;
    if (c < 40) {
        float inv = 1.f / (float)n;
        float sum = bp[c];
        for (int k = 0; k < HD; k++) sum = fmaf(g_hg[k] * inv, Wp[c * HD + k], sum);
        out[c] = sum;
    }
}

// ---- CAM via HMMA: out[c*n + node] = dot(Wp[c,:], H[node,:]); fused column-sum of H ----
__global__ void __launch_bounds__(256) k_cam(const __half* __restrict__ Hh,
                                             float* __restrict__ out, int n) {
    extern __shared__ __half sh[];
    __half* As = sh;                    // 128 x SSTR (H tile)
    __half* Bs = sh + 128 * SSTR;       // 64 x SSTR (Wp fp16, padded)
    float*  Ts = (float*)sh;            // 128 x 65 fp32 (overlays As/Bs after mma)
    int tid = threadIdx.x;
    int base = blockIdx.x * 128;

    // ---- load H tile ----
    const uint4* H4 = (const uint4*)Hh;
    #pragma unroll
    for (int i = 0; i < 8; i++) {
        int slot = i * 256 + tid;
        int row = slot >> 4, j = slot & 15;
        int gr = base + row;
        uint4 v = make_uint4(0u, 0u, 0u, 0u);
        if (gr < n) v = H4[gr * 16 + j];
        *(uint4*)(As + row * SSTR + j * 8) = v;
    }
    // ---- load Wp fp16 (64 x 128, rows 40..63 zero) ----
    const uint4* P4 = (const uint4*)g_wpt;
    #pragma unroll
    for (int i = 0; i < 4; i++) {
        int slot = i * 256 + tid;           // 1024 slots
        int row = slot >> 4, j = slot & 15;
        uint4 v = P4[slot];
        *(uint4*)(Bs + row * SSTR + j * 8) = v;
    }
    __syncthreads();

    int lane = tid & 31;
    int w = tid >> 5;
    int wm = (w & 3) * 32;     // node rows
    int wn = (w >> 2) * 32;    // class cols

    float acc[2][4][4];
    #pragma unroll
    for (int mi = 0; mi < 2; mi++)
        #pragma unroll
        for (int ni = 0; ni < 4; ni++)
            #pragma unroll
            for (int q = 0; q < 4; q++) acc[mi][ni][q] = 0.f;

    uint32_t a_base = smem_u32(As);
    uint32_t b_base = smem_u32(Bs);

    #pragma unroll
    for (int k0 = 0; k0 < 128; k0 += 16) {
        uint32_t af[2][4];
        #pragma unroll
        for (int mi = 0; mi < 2; mi++) {
            int row = wm + mi * 16 + (lane & 15);
            int col = k0 + (lane >> 4) * 8;
            ldsm_x4(af[mi], a_base + (uint32_t)(row * SSTR + col) * 2);
        }
        uint32_t bf[2][4];
        #pragma unroll
        for (int p = 0; p < 2; p++) {
            int row = wn + p * 16 + ((lane >> 4) & 1) * 8 + (lane & 7);
            int col = k0 + ((lane >> 3) & 1) * 8;
            ldsm_x4(bf[p], b_base + (uint32_t)(row * SSTR + col) * 2);
        }
        #pragma unroll
        for (int mi = 0; mi < 2; mi++)
            #pragma unroll
            for (int p = 0; p < 2; p++) {
                mma_f16(acc[mi][2 * p],     af[mi], bf[p][0], bf[p][1]);
                mma_f16(acc[mi][2 * p + 1], af[mi], bf[p][2], bf[p][3]);
            }
    }

    // ---- fused column sum of this block's H tile (zeros beyond n are harmless) ----
    if (tid < 128) {
        float s = 0.f;
        #pragma unroll 8
        for (int r = 0; r < 128; r++) s += __half2float(As[r * SSTR + tid]);
        atomicAdd(&g_hg[tid], s);
    }
    __syncthreads();   // all reads of As/Bs done before Ts overwrite

    // ---- fragments -> padded fp32 smem tile ----
    #pragma unroll
    for (int mi = 0; mi < 2; mi++) {
        int r0 = wm + mi * 16 + (lane >> 2);
        int r1 = r0 + 8;
        #pragma unroll
        for (int ni = 0; ni < 4; ni++) {
            int col = wn + ni * 8 + (lane & 3) * 2;
            Ts[r0 * 65 + col]     = acc[mi][ni][0];
            Ts[r0 * 65 + col + 1] = acc[mi][ni][1];
            Ts[r1 * 65 + col]     = acc[mi][ni][2];
            Ts[r1 * 65 + col + 1] = acc[mi][ni][3];
        }
    }
    __syncthreads();

    // ---- coalesced transposed store: out[c*n + node] ----
    for (int idx = tid; idx < 40 * 128; idx += 256) {
        int c = idx >> 7, i = idx & 127;
        int node = base + i;
        if (node < n) out[c * n + node] = Ts[i * 65 + c];
    }
}

// ---------------- launch ----------------
extern "C" void kernel_launch(void* const* d_in, const int* in_sizes, int n_in,
                              void* d_out, int out_size) {
    const float* features = (const float*)d_in[0];
    const float* W1 = (const float*)d_in[1];
    const float* b1 = (const float*)d_in[2];
    const float* W2 = (const float*)d_in[3];
    const float* b2 = (const float*)d_in[4];
    const float* W3 = (const float*)d_in[5];
    const float* b3 = (const float*)d_in[6];
    const float* Wp = (const float*)d_in[7];
    const float* bp = (const float*)d_in[8];
    const int*  src = (const int*)d_in[9];
    const int*  dst = (const int*)d_in[10];
    float* out = (float*)d_out;

    int n = in_sizes[0] / HD;          // 100000
    int e = in_sizes[9];               // 1600000

    int ge  = (e + 255) / 256;
    int nb  = (n + 511) / 512;

    __half *h16a, *h16b, *m16, *wt1, *wt2, *wt3;
    void *degout, *degin, *hg;
    cudaGetSymbolAddress((void**)&h16a, g_h16a);
    cudaGetSymbolAddress((void**)&h16b, g_h16b);
    cudaGetSymbolAddress((void**)&m16,  g_m16);
    cudaGetSymbolAddress((void**)&wt1,  g_wt1);
    cudaGetSymbolAddress((void**)&wt2,  g_wt2);
    cudaGetSymbolAddress((void**)&wt3,  g_wt3);
    cudaGetSymbolAddress(&degout, g_degout);
    cudaGetSymbolAddress(&degin,  g_degin);
    cudaGetSymbolAddress(&hg,     g_hg);

    cudaFuncSetAttribute(k_mm,  cudaFuncAttributeMaxDynamicSharedMemorySize, MM_SMEM);
    cudaFuncSetAttribute(k_cam, cudaFuncAttributeMaxDynamicSharedMemorySize, CAM_SMEM);

    cudaMemsetAsync(degout, 0, n * sizeof(int));
    cudaMemsetAsync(degin,  0, n * sizeof(int));
    cudaMemsetAsync(hg,     0, HD * sizeof(float));

    int gt = (n + 127) / 128;   // GEMM / CAM tiles
    int ga = (n + 7) / 8;

    k_deg<<<(e / 2 + 255) / 256, 256>>>(src, dst, e);                               // 1
    k_prepall<<<96 + (n * 32 + 255) / 256, 256>>>(W1, W2, W3, Wp, features, h16a, n); // 2
    k_scan1<<<nb, 512>>>(n);                                                        // 3
    k_mm<<<gt, 256, MM_SMEM>>>(h16a, wt1, m16, n);                                  // 4 <- ncu profiles this
    k_scan3<<<nb, 512>>>(nb, n);                                                    // 5
    k_scatter<<<ge, 256>>>(src, dst, e);                                            // 6
    k_agg_h<<<ga, 256>>>(m16, b1, h16b, n);                                         // 7
    k_mm<<<gt, 256, MM_SMEM>>>(h16b, wt2, m16, n);                                  // 8
    k_agg_h<<<ga, 256>>>(m16, b2, h16a, n);                                         // 9
    k_mm<<<gt, 256, MM_SMEM>>>(h16a, wt3, m16, n);                                  // 10
    k_agg_o<<<ga, 256>>>(m16, b3, h16b, n);                                         // 11

    // heads (fp16 H in h16b): cam fuses colsum; seg reads g_hg after cam
    k_cam<<<gt, 256, CAM_SMEM>>>(h16b, out + 40, n);                                // 12
    k_seg<<<1, 64>>>(Wp, bp, out, n);                                               // 13
}